// round 3
// baseline (speedup 1.0000x reference)
#include <cuda_runtime.h>
#include <math.h>
#include <stdint.h>

// Problem shapes (fixed per reference)
#define PB 2048
#define PS 32
#define PD 1024
#define PH 1024
#define PM 4096
#define PK 32

// ---------------- scratch (device globals; no runtime allocation) ----------
__device__ float g_enc[(size_t)PB * PS * PH];     // 268 MB
__device__ float g_query[(size_t)PB * PH];        // 8 MB
__device__ float g_sim[(size_t)PB * PM];          // 32 MB  (raw sim == act round-0 input)
__device__ float g_prob[(size_t)PB * PM];         // 32 MB
__device__ float g_act[(size_t)PB * PM];          // 32 MB
__device__ float g_gate[PB];
__device__ float g_vals[PB * PK];
__device__ int   g_idx[PB * PK];
__device__ float g_read[(size_t)PB * PH];         // 8 MB
__device__ float g_osmall[(size_t)PB * PD];       // 8 MB

// ---------------- generic 128x128x8 register-blocked SGEMM -----------------
// C[M,N] = A[M,K] (row-major) * B
//   B_NK = true : B is [N,K] row-major (dot of rows; "NT")
//   B_NK = false: B is [K,N] row-major ("NN")
// EPI: 0 = plain store, 1 = tanh(c + bias[n])
// All of M,N multiples of 128; K multiple of 8. (Holds for every call here.)
#define BM 128
#define BN 128
#define BKK 8
#define TM 8
#define TN 8

template <int EPI, bool B_NK>
__global__ __launch_bounds__(256)
void sgemm_kernel(const float* __restrict__ A, const float* __restrict__ B,
                  const float* __restrict__ bias, float* __restrict__ C,
                  int M, int N, int K)
{
    __shared__ float As[BKK][BM];
    __shared__ float Bs[BKK][BN];

    const int tid = threadIdx.x;
    const int bx = blockIdx.x;   // N tile
    const int by = blockIdx.y;   // M tile

    const float* Ablk = A + (size_t)by * BM * K;

    const int tx = tid % 16;
    const int ty = tid / 16;

    // A tile load mapping: 128 rows x 8 cols, one float4 per thread
    const int a_row = tid >> 1;          // 0..127
    const int a_col = (tid & 1) * 4;     // 0 or 4

    float acc[TM][TN];
#pragma unroll
    for (int i = 0; i < TM; i++)
#pragma unroll
        for (int j = 0; j < TN; j++) acc[i][j] = 0.f;

    for (int k0 = 0; k0 < K; k0 += BKK) {
        // load A tile (transposed into smem)
        float4 av = *(const float4*)(Ablk + (size_t)a_row * K + k0 + a_col);
        As[a_col + 0][a_row] = av.x;
        As[a_col + 1][a_row] = av.y;
        As[a_col + 2][a_row] = av.z;
        As[a_col + 3][a_row] = av.w;

        // load B tile
        if (B_NK) {
            const int n = tid >> 1;              // 0..127 (local n)
            const int c = (tid & 1) * 4;         // k offset
            float4 bv = *(const float4*)(B + (size_t)(bx * BN + n) * K + k0 + c);
            Bs[c + 0][n] = bv.x;
            Bs[c + 1][n] = bv.y;
            Bs[c + 2][n] = bv.z;
            Bs[c + 3][n] = bv.w;
        } else {
            const int kk = tid >> 5;             // 0..7
            const int n4 = (tid & 31) * 4;       // 0..124
            float4 bv = *(const float4*)(B + (size_t)(k0 + kk) * N + bx * BN + n4);
            *(float4*)&Bs[kk][n4] = bv;
        }
        __syncthreads();

#pragma unroll
        for (int k = 0; k < BKK; k++) {
            float a[TM], b[TN];
#pragma unroll
            for (int i = 0; i < TM; i++) a[i] = As[k][ty * TM + i];
#pragma unroll
            for (int j = 0; j < TN; j++) b[j] = Bs[k][tx * TN + j];
#pragma unroll
            for (int i = 0; i < TM; i++)
#pragma unroll
                for (int j = 0; j < TN; j++) acc[i][j] += a[i] * b[j];
        }
        __syncthreads();
    }

    const int crow0 = by * BM + ty * TM;
    const int ccol0 = bx * BN + tx * TN;
#pragma unroll
    for (int i = 0; i < TM; i++) {
        float out[TN];
#pragma unroll
        for (int j = 0; j < TN; j++) {
            float v = acc[i][j];
            if (EPI == 1) v = tanhf(v + bias[ccol0 + j]);
            out[j] = v;
        }
        float* crow = C + (size_t)(crow0 + i) * N + ccol0;
        *(float4*)(crow + 0) = *(float4*)&out[0];
        *(float4*)(crow + 4) = *(float4*)&out[4];
    }
}

// ---------------- mean over S ----------------------------------------------
__global__ __launch_bounds__(256)
void mean_kernel(const float* __restrict__ enc, float* __restrict__ query)
{
    const int b = blockIdx.x;
    for (int h = threadIdx.x; h < PH; h += 256) {
        float s = 0.f;
        const float* p = enc + ((size_t)b * PS) * PH + h;
#pragma unroll 8
        for (int ss = 0; ss < PS; ss++) s += p[(size_t)ss * PH];
        query[(size_t)b * PH + h] = s * (1.0f / (float)PS);
    }
}

// ---------------- gate = sigmoid(query @ w_curv + b_curv) ------------------
__global__ __launch_bounds__(256)
void gate_kernel(const float* __restrict__ query, const float* __restrict__ w_curv,
                 const float* __restrict__ b_curv, float* __restrict__ gate)
{
    const int b = blockIdx.x;
    const int tid = threadIdx.x;
    float s = 0.f;
    for (int h = tid; h < PH; h += 256) s += query[(size_t)b * PH + h] * w_curv[h];
    __shared__ float red[256];
    red[tid] = s;
    __syncthreads();
    for (int off = 128; off > 0; off >>= 1) {
        if (tid < off) red[tid] += red[tid + off];
        __syncthreads();
    }
    if (tid == 0) {
        float z = red[0] + b_curv[0];
        gate[b] = 1.f / (1.f + expf(-z));
    }
}

// ---------------- top-k (K=32) over M=4096, iterative argmax ---------------
__global__ __launch_bounds__(256)
void topk_kernel(const float* __restrict__ sim, float* __restrict__ vals,
                 int* __restrict__ idx)
{
    __shared__ float sv[PM];
    __shared__ float rv[256];
    __shared__ int   ri[256];
    const int b = blockIdx.x;
    const int tid = threadIdx.x;

    for (int m = tid; m < PM; m += 256) sv[m] = sim[(size_t)b * PM + m];
    __syncthreads();

    for (int k = 0; k < PK; k++) {
        float best = -INFINITY;
        int bi = PM;
        for (int m = tid; m < PM; m += 256) {
            float v = sv[m];
            if (v > best) { best = v; bi = m; }   // scan order => smallest m on ties
        }
        rv[tid] = best; ri[tid] = bi;
        __syncthreads();
        for (int off = 128; off > 0; off >>= 1) {
            if (tid < off) {
                float ov = rv[tid + off]; int oi = ri[tid + off];
                if (ov > rv[tid] || (ov == rv[tid] && oi < ri[tid])) { rv[tid] = ov; ri[tid] = oi; }
            }
            __syncthreads();
        }
        if (tid == 0) {
            vals[b * PK + k] = rv[0];   // RAW value (scale applied later; scale > 0)
            idx[b * PK + k]  = ri[0];
            sv[ri[0]] = -INFINITY;
        }
        __syncthreads();
    }
}

// ---------------- row softmax over M=4096 ----------------------------------
__global__ __launch_bounds__(256)
void softmax_kernel(const float* __restrict__ in, float* __restrict__ out)
{
    const int b = blockIdx.x;
    const int tid = threadIdx.x;
    float loc[PM / 256];
    float mx = -INFINITY;
#pragma unroll
    for (int i = 0; i < PM / 256; i++) {
        loc[i] = in[(size_t)b * PM + tid + i * 256];
        mx = fmaxf(mx, loc[i]);
    }
    __shared__ float red[256];
    red[tid] = mx;
    __syncthreads();
    for (int off = 128; off > 0; off >>= 1) {
        if (tid < off) red[tid] = fmaxf(red[tid], red[tid + off]);
        __syncthreads();
    }
    mx = red[0];
    __syncthreads();
    float sum = 0.f;
#pragma unroll
    for (int i = 0; i < PM / 256; i++) {
        loc[i] = expf(loc[i] - mx);
        sum += loc[i];
    }
    red[tid] = sum;
    __syncthreads();
    for (int off = 128; off > 0; off >>= 1) {
        if (tid < off) red[tid] += red[tid + off];
        __syncthreads();
    }
    float inv = 1.f / red[0];
#pragma unroll
    for (int i = 0; i < PM / 256; i++)
        out[(size_t)b * PM + tid + i * 256] = loc[i] * inv;
}

// ---------------- comb softmax + weighted gather-read ----------------------
__global__ __launch_bounds__(256)
void read_kernel(const float* __restrict__ vals, const int* __restrict__ idx,
                 const float* __restrict__ act, const float* __restrict__ gate,
                 const float* __restrict__ temperature, const float* __restrict__ mem,
                 float* __restrict__ readout)
{
    const int b = blockIdx.x;
    const int tid = threadIdx.x;
    __shared__ float comb[PK];
    __shared__ int   sidx[PK];

    if (tid < PK) {
        const float scale = (0.5f + gate[b]) / fmaxf(temperature[0], 1e-6f);
        const int id = idx[b * PK + tid];
        sidx[tid] = id;
        float v = vals[b * PK + tid] * scale + act[(size_t)b * PM + id];
        // warp softmax over 32 lanes (whole warp 0 participates)
        float mx = v;
#pragma unroll
        for (int o = 16; o > 0; o >>= 1) mx = fmaxf(mx, __shfl_xor_sync(0xffffffffu, mx, o));
        float e = expf(v - mx);
        float s = e;
#pragma unroll
        for (int o = 16; o > 0; o >>= 1) s += __shfl_xor_sync(0xffffffffu, s, o);
        comb[tid] = e / s;
    }
    __syncthreads();

    for (int h = tid; h < PH; h += 256) {
        float accv = 0.f;
#pragma unroll
        for (int k = 0; k < PK; k++)
            accv += comb[k] * mem[(size_t)sidx[k] * PH + h];
        readout[(size_t)b * PH + h] = accv;
    }
}

// ---------------- broadcast [B,D] -> [B,S,D] -------------------------------
__global__ __launch_bounds__(256)
void bcast_kernel(const float* __restrict__ small, float* __restrict__ out)
{
    // index space over float4s of the output: B * S * (D/4)
    const size_t i = (size_t)blockIdx.x * blockDim.x + threadIdx.x;
    const int c = (int)(i & (PD / 4 - 1));                 // 0..255
    const size_t bs = i / (PD / 4);                        // b*S + s
    const size_t b = bs / PS;
    float4 v = ((const float4*)small)[b * (PD / 4) + c];
    ((float4*)out)[i] = v;
}

// ---------------- launch ----------------------------------------------------
extern "C" void kernel_launch(void* const* d_in, const int* in_sizes, int n_in,
                              void* d_out, int out_size)
{
    const float* x      = (const float*)d_in[0];
    // d_in[1] = topk (int, fixed 32)
    const float* W_enc  = (const float*)d_in[2];
    const float* b_enc  = (const float*)d_in[3];
    const float* w_curv = (const float*)d_in[4];
    const float* b_curv = (const float*)d_in[5];
    const float* memsl  = (const float*)d_in[6];
    const float* assoc  = (const float*)d_in[7];
    const float* W_dec  = (const float*)d_in[8];
    const float* b_dec  = (const float*)d_in[9];
    const float* temp   = (const float*)d_in[10];
    float* out = (float*)d_out;

    float *enc, *query, *sim, *prob, *act, *gate, *vals, *readb, *osmall;
    int* idxp;
    cudaGetSymbolAddress((void**)&enc,    g_enc);
    cudaGetSymbolAddress((void**)&query,  g_query);
    cudaGetSymbolAddress((void**)&sim,    g_sim);
    cudaGetSymbolAddress((void**)&prob,   g_prob);
    cudaGetSymbolAddress((void**)&act,    g_act);
    cudaGetSymbolAddress((void**)&gate,   g_gate);
    cudaGetSymbolAddress((void**)&vals,   g_vals);
    cudaGetSymbolAddress((void**)&idxp,   g_idx);
    cudaGetSymbolAddress((void**)&readb,  g_read);
    cudaGetSymbolAddress((void**)&osmall, g_osmall);

    // 1. enc = tanh(x @ W_enc + b_enc)   [65536,1024] x [1024,1024]
    sgemm_kernel<1, false><<<dim3(PH / BN, (PB * PS) / BM), 256>>>(
        x, W_enc, b_enc, enc, PB * PS, PH, PD);

    // 2. query = mean_S(enc)
    mean_kernel<<<PB, 256>>>(enc, query);

    // 3. sim_raw = query @ mem^T  (also the round-0 "act" input)
    sgemm_kernel<0, true><<<dim3(PM / BN, PB / BM), 256>>>(
        query, memsl, nullptr, sim, PB, PM, PH);

    // 4. gate
    gate_kernel<<<PB, 256>>>(query, w_curv, b_curv, gate);

    // 5. top-k on raw sim (scale is positive => same ordering)
    topk_kernel<<<PB, 256>>>(sim, vals, idxp);

    // 6. two rounds of softmax -> @assoc
    softmax_kernel<<<PB, 256>>>(sim, prob);
    sgemm_kernel<0, false><<<dim3(PM / BN, PB / BM), 256>>>(
        prob, assoc, nullptr, act, PB, PM, PM);
    softmax_kernel<<<PB, 256>>>(act, prob);
    sgemm_kernel<0, false><<<dim3(PM / BN, PB / BM), 256>>>(
        prob, assoc, nullptr, act, PB, PM, PM);

    // 7. comb softmax + weighted memory read
    read_kernel<<<PB, 256>>>(vals, idxp, act, gate, temp, memsl, readb);

    // 8. out_small = tanh(read @ W_dec + b_dec)
    sgemm_kernel<1, false><<<dim3(PD / BN, PB / BM), 256>>>(
        readb, W_dec, b_dec, osmall, PB, PD, PH);

    // 9. broadcast to [B,S,D]
    bcast_kernel<<<(PB * PS * (PD / 4)) / 256, 256>>>(osmall, out);
}

// round 5
// speedup vs baseline: 3.2802x; 3.2802x over previous
#include <cuda_runtime.h>
#include <cuda_bf16.h>
#include <math.h>
#include <stdint.h>

// Problem shapes (fixed per reference)
#define PB 2048
#define PS 32
#define PD 1024
#define PH 1024
#define PM 4096
#define PK 32

// ===================== low-level helpers ====================================
__device__ __forceinline__ uint32_t smem_to_u32(const void* p) {
    uint32_t a;
    asm("{ .reg .u64 t; cvta.to.shared.u64 t, %1; cvt.u32.u64 %0, t; }" : "=r"(a) : "l"(p));
    return a;
}
__device__ __forceinline__ void ldsm_x4(uint32_t* r, uint32_t addr) {
    asm volatile("ldmatrix.sync.aligned.m8n8.x4.shared.b16 {%0,%1,%2,%3}, [%4];"
                 : "=r"(r[0]), "=r"(r[1]), "=r"(r[2]), "=r"(r[3]) : "r"(addr));
}
__device__ __forceinline__ void mma_bf16(float* d, const uint32_t* a, const uint32_t* b) {
    asm volatile(
        "mma.sync.aligned.m16n8k16.row.col.f32.bf16.bf16.f32 "
        "{%0,%1,%2,%3}, {%4,%5,%6,%7}, {%8,%9}, {%0,%1,%2,%3};\n"
        : "+f"(d[0]), "+f"(d[1]), "+f"(d[2]), "+f"(d[3])
        : "r"(a[0]), "r"(a[1]), "r"(a[2]), "r"(a[3]), "r"(b[0]), "r"(b[1]));
}
__device__ __forceinline__ void cpasync16(uint32_t s, const void* g) {
    asm volatile("cp.async.cg.shared.global [%0], [%1], 16;" :: "r"(s), "l"(g));
}
__device__ __forceinline__ void cp_commit() {
    asm volatile("cp.async.commit_group;" ::: "memory");
}

// ===================== scratch (device globals) =============================
__device__ float g_query[(size_t)PB * PH];
__device__ float g_sim[(size_t)PB * PM];
__device__ float g_prob[(size_t)PB * PM];
__device__ float g_act[(size_t)PB * PM];
__device__ float g_gate[PB];
__device__ float g_vals[PB * PK];
__device__ int   g_idx[PB * PK];
__device__ float g_read[(size_t)PB * PH];
__device__ float g_osmall[(size_t)PB * PD];

__device__ __nv_bfloat16 g_wencT_h[(size_t)PH * PD];
__device__ __nv_bfloat16 g_wencT_l[(size_t)PH * PD];
__device__ __nv_bfloat16 g_assocT_h[(size_t)PM * PM];
__device__ __nv_bfloat16 g_assocT_l[(size_t)PM * PM];
__device__ __nv_bfloat16 g_wdecT_h[(size_t)PD * PH];
__device__ __nv_bfloat16 g_wdecT_l[(size_t)PD * PH];
__device__ __nv_bfloat16 g_memT_h[(size_t)PM * PH];
__device__ __nv_bfloat16 g_memT_l[(size_t)PM * PH];

// ===================== bf16 hi/lo split helpers =============================
__device__ __forceinline__ void split4(float4 v, uint2& hi, uint2& lo) {
    __nv_bfloat16 h0 = __float2bfloat16_rn(v.x);
    __nv_bfloat16 h1 = __float2bfloat16_rn(v.y);
    __nv_bfloat16 h2 = __float2bfloat16_rn(v.z);
    __nv_bfloat16 h3 = __float2bfloat16_rn(v.w);
    __nv_bfloat16 l0 = __float2bfloat16_rn(v.x - __bfloat162float(h0));
    __nv_bfloat16 l1 = __float2bfloat16_rn(v.y - __bfloat162float(h1));
    __nv_bfloat16 l2 = __float2bfloat16_rn(v.z - __bfloat162float(h2));
    __nv_bfloat16 l3 = __float2bfloat16_rn(v.w - __bfloat162float(h3));
    hi.x = (uint32_t)__bfloat16_as_ushort(h0) | ((uint32_t)__bfloat16_as_ushort(h1) << 16);
    hi.y = (uint32_t)__bfloat16_as_ushort(h2) | ((uint32_t)__bfloat16_as_ushort(h3) << 16);
    lo.x = (uint32_t)__bfloat16_as_ushort(l0) | ((uint32_t)__bfloat16_as_ushort(l1) << 16);
    lo.y = (uint32_t)__bfloat16_as_ushort(l2) | ((uint32_t)__bfloat16_as_ushort(l3) << 16);
}
__device__ __forceinline__ void hi4(float4 v, uint2& hi) {
    __nv_bfloat16 h0 = __float2bfloat16_rn(v.x);
    __nv_bfloat16 h1 = __float2bfloat16_rn(v.y);
    __nv_bfloat16 h2 = __float2bfloat16_rn(v.z);
    __nv_bfloat16 h3 = __float2bfloat16_rn(v.w);
    hi.x = (uint32_t)__bfloat16_as_ushort(h0) | ((uint32_t)__bfloat16_as_ushort(h1) << 16);
    hi.y = (uint32_t)__bfloat16_as_ushort(h2) | ((uint32_t)__bfloat16_as_ushort(h3) << 16);
}

// ===================== weight prep kernels ==================================
// in [K][N] fp32 row-major -> out hi/lo [N][K] bf16 (transpose + split)
__global__ __launch_bounds__(256)
void transpose_split_kernel(const float* __restrict__ in, __nv_bfloat16* __restrict__ oh,
                            __nv_bfloat16* __restrict__ ol, int K, int N)
{
    __shared__ float t[32][33];
    const int tx = threadIdx.x & 31, ty = threadIdx.x >> 5;
    const int n_base = blockIdx.x * 32, k_base = blockIdx.y * 32;
#pragma unroll
    for (int j = 0; j < 4; j++) {
        int k = k_base + ty + j * 8;
        t[ty + j * 8][tx] = in[(size_t)k * N + n_base + tx];
    }
    __syncthreads();
#pragma unroll
    for (int j = 0; j < 4; j++) {
        int n = n_base + ty + j * 8;
        int k = k_base + tx;
        float v = t[tx][ty + j * 8];
        __nv_bfloat16 h = __float2bfloat16_rn(v);
        __nv_bfloat16 l = __float2bfloat16_rn(v - __bfloat162float(h));
        oh[(size_t)n * K + k] = h;
        ol[(size_t)n * K + k] = l;
    }
}

// already [N][K]: split only (float4 -> 2x uint2 bf16)
__global__ __launch_bounds__(256)
void split_kernel(const float* __restrict__ in, __nv_bfloat16* __restrict__ oh,
                  __nv_bfloat16* __restrict__ ol)
{
    const size_t i = (size_t)blockIdx.x * 256 + threadIdx.x;
    float4 v = ((const float4*)in)[i];
    uint2 hi, lo;
    split4(v, hi, lo);
    ((uint2*)oh)[i] = hi;
    ((uint2*)ol)[i] = lo;
}

// ===================== tensor-core GEMM via mma.sync ========================
// C[M,N] = A[M,K] fp32 (split on fly) * B^T, B pre-split [N][K] bf16 hi/lo.
// SPLIT=1: bf16x3 (Ah.Bh + Al.Bh + Ah.Bl)   SPLIT=0: pure bf16 (Ah.Bh)
// Tile 128x128, BK=32, 256 threads (8 warps of 64x32), double-buffered smem.
// EPI 0: store C    EPI 1: C = tanh(c + bias[n])
// EPI 2: Q[b][n] = mean over 32-row groups of tanh(c + bias[n])
#define MPAD 80          // bytes per smem row (32 bf16 + 8 pad)
#define OFF_AH 0u
#define OFF_AL 10240u
#define OFF_BH 20480u
#define OFF_BL 30720u
#define MSTAGE 40960u
#define MSMEM  81920u

template <int EPI, int SPLIT>
__global__ __launch_bounds__(256)
void gemm_mma(const float* __restrict__ A, const __nv_bfloat16* __restrict__ Bh,
              const __nv_bfloat16* __restrict__ Bl, const float* __restrict__ bias,
              float* __restrict__ C, float* __restrict__ Q, int M, int N, int K)
{
    extern __shared__ char sm[];
    const uint32_t smb = smem_to_u32(sm);
    const int tid = threadIdx.x, wid = tid >> 5, lane = tid & 31;
    const int m0 = blockIdx.y * 128, n0 = blockIdx.x * 128;
    const int wm = (wid >> 2) * 64, wn = (wid & 3) * 32;

    float acc[4][4][4];
#pragma unroll
    for (int i = 0; i < 4; i++)
#pragma unroll
        for (int j = 0; j < 4; j++)
#pragma unroll
            for (int q = 0; q < 4; q++) acc[i][j][q] = 0.f;

    const float* Ag = A + (size_t)m0 * K;

    // ldmatrix per-lane address components
    const int lr = lane & 15;
    const int kh = (lane >> 4) ? 8 : 0;                    // A k-half
    const int br = (lane & 7) + ((lane & 16) ? 8 : 0);     // B n-row within 16
    const int bk = (lane & 8) ? 8 : 0;                     // B k-half

    const int nch = K >> 5;
    float4 areg[4];

    // -------- prologue: B(0) cp.async, A(0) LDG ----------------------------
    {
        const int nb = SPLIT ? 4 : 2;
#pragma unroll
        for (int i = 0; i < 4; i++) {
            if (i < nb) {
                int id = tid + i * 256;
                int half = id >> 9, row = (id & 511) >> 2, ch = id & 3;
                const __nv_bfloat16* src =
                    (half ? Bl : Bh) + (size_t)(n0 + row) * K + ch * 8;
                uint32_t dst = smb + OFF_BH + half * 10240u + row * MPAD + ch * 16;
                cpasync16(dst, src);
            }
        }
        cp_commit();
#pragma unroll
        for (int i = 0; i < 4; i++) {
            int id = tid + i * 256;
            int row = id >> 3, c4 = id & 7;
            areg[i] = *(const float4*)(Ag + (size_t)row * K + c4 * 4);
        }
    }

    for (int c = 0; c < nch; c++) {
        const int buf = c & 1;
        const uint32_t sb = smb + buf * MSTAGE;
        char* sp = sm + buf * MSTAGE;

        // split + store A tile
#pragma unroll
        for (int i = 0; i < 4; i++) {
            int id = tid + i * 256;
            int row = id >> 3, c4 = id & 7;
            if (SPLIT) {
                uint2 hi, lo;
                split4(areg[i], hi, lo);
                *(uint2*)(sp + OFF_AH + row * MPAD + c4 * 8) = hi;
                *(uint2*)(sp + OFF_AL + row * MPAD + c4 * 8) = lo;
            } else {
                uint2 hi;
                hi4(areg[i], hi);
                *(uint2*)(sp + OFF_AH + row * MPAD + c4 * 8) = hi;
            }
        }

        // issue next B tile into other buffer
        if (c + 1 < nch) {
            const int k0n = (c + 1) << 5;
            const uint32_t so = smb + (buf ^ 1) * MSTAGE;
            const int nb = SPLIT ? 4 : 2;
#pragma unroll
            for (int i = 0; i < 4; i++) {
                if (i < nb) {
                    int id = tid + i * 256;
                    int half = id >> 9, row = (id & 511) >> 2, ch = id & 3;
                    const __nv_bfloat16* src =
                        (half ? Bl : Bh) + (size_t)(n0 + row) * K + k0n + ch * 8;
                    uint32_t dst = so + OFF_BH + half * 10240u + row * MPAD + ch * 16;
                    cpasync16(dst, src);
                }
            }
            cp_commit();
            asm volatile("cp.async.wait_group 1;" ::: "memory");
        } else {
            asm volatile("cp.async.wait_group 0;" ::: "memory");
        }
        __syncthreads();

        // prefetch next A tile (LDG overlaps compute)
        if (c + 1 < nch) {
            const int k0n = (c + 1) << 5;
#pragma unroll
            for (int i = 0; i < 4; i++) {
                int id = tid + i * 256;
                int row = id >> 3, c4 = id & 7;
                areg[i] = *(const float4*)(Ag + (size_t)row * K + k0n + c4 * 4);
            }
        }

        // -------- compute this tile ----------------------------------------
#pragma unroll
        for (int ks = 0; ks < 2; ks++) {
            uint32_t ah[4][4], bhf[2][4];
#pragma unroll
            for (int mt = 0; mt < 4; mt++)
                ldsm_x4(ah[mt], sb + OFF_AH + (wm + mt * 16 + lr) * MPAD + (ks * 16 + kh) * 2);
#pragma unroll
            for (int p = 0; p < 2; p++)
                ldsm_x4(bhf[p], sb + OFF_BH + (wn + p * 16 + br) * MPAD + (ks * 16 + bk) * 2);
#pragma unroll
            for (int mt = 0; mt < 4; mt++)
#pragma unroll
                for (int nt = 0; nt < 4; nt++)
                    mma_bf16(acc[mt][nt], ah[mt], &bhf[nt >> 1][(nt & 1) * 2]);
            if (SPLIT) {
                uint32_t al[4][4];
#pragma unroll
                for (int mt = 0; mt < 4; mt++)
                    ldsm_x4(al[mt], sb + OFF_AL + (wm + mt * 16 + lr) * MPAD + (ks * 16 + kh) * 2);
#pragma unroll
                for (int mt = 0; mt < 4; mt++)
#pragma unroll
                    for (int nt = 0; nt < 4; nt++)
                        mma_bf16(acc[mt][nt], al[mt], &bhf[nt >> 1][(nt & 1) * 2]);
                uint32_t blf[2][4];
#pragma unroll
                for (int p = 0; p < 2; p++)
                    ldsm_x4(blf[p], sb + OFF_BL + (wn + p * 16 + br) * MPAD + (ks * 16 + bk) * 2);
#pragma unroll
                for (int mt = 0; mt < 4; mt++)
#pragma unroll
                    for (int nt = 0; nt < 4; nt++)
                        mma_bf16(acc[mt][nt], ah[mt], &blf[nt >> 1][(nt & 1) * 2]);
            }
        }
        __syncthreads();
    }

    // -------- epilogue: regs -> smem (padded) -> gmem -----------------------
    float* smf = (float*)sm;   // 128 x 132 floats (67.6 KB <= 80 KB)
#pragma unroll
    for (int mt = 0; mt < 4; mt++) {
#pragma unroll
        for (int nt = 0; nt < 4; nt++) {
            int r = wm + mt * 16 + (lane >> 2);
            int cc = wn + nt * 8 + (lane & 3) * 2;
            float v0 = acc[mt][nt][0], v1 = acc[mt][nt][1];
            float v2 = acc[mt][nt][2], v3 = acc[mt][nt][3];
            if (EPI >= 1) {
                float b0 = bias[n0 + cc], b1 = bias[n0 + cc + 1];
                v0 = tanhf(v0 + b0); v1 = tanhf(v1 + b1);
                v2 = tanhf(v2 + b0); v3 = tanhf(v3 + b1);
            }
            smf[r * 132 + cc] = v0;
            smf[r * 132 + cc + 1] = v1;
            smf[(r + 8) * 132 + cc] = v2;
            smf[(r + 8) * 132 + cc + 1] = v3;
        }
    }
    __syncthreads();

    if (EPI == 2) {
#pragma unroll
        for (int i = 0; i < 2; i++) {
            int task = tid + i * 256;           // 512 tasks: 4 groups x 128 cols
            int grp = task >> 7, col = task & 127;
            float s = 0.f;
#pragma unroll
            for (int rr = 0; rr < 32; rr++) s += smf[(grp * 32 + rr) * 132 + col];
            Q[(size_t)(blockIdx.y * 4 + grp) * N + n0 + col] = s * (1.0f / 32.0f);
        }
    } else {
#pragma unroll
        for (int i = 0; i < 16; i++) {
            int id = tid + i * 256;             // 4096 float4 ids
            int row = id >> 5, c4 = id & 31;
            float4 o;
            o.x = smf[row * 132 + c4 * 4 + 0];
            o.y = smf[row * 132 + c4 * 4 + 1];
            o.z = smf[row * 132 + c4 * 4 + 2];
            o.w = smf[row * 132 + c4 * 4 + 3];
            *(float4*)(C + (size_t)(m0 + row) * N + n0 + c4 * 4) = o;
        }
    }
}

// ===================== small kernels (from passing R2) ======================
__global__ __launch_bounds__(256)
void gate_kernel(const float* __restrict__ query, const float* __restrict__ w_curv,
                 const float* __restrict__ b_curv, float* __restrict__ gate)
{
    const int b = blockIdx.x;
    const int tid = threadIdx.x;
    float s = 0.f;
    for (int h = tid; h < PH; h += 256) s += query[(size_t)b * PH + h] * w_curv[h];
    __shared__ float red[256];
    red[tid] = s;
    __syncthreads();
    for (int off = 128; off > 0; off >>= 1) {
        if (tid < off) red[tid] += red[tid + off];
        __syncthreads();
    }
    if (tid == 0) {
        float z = red[0] + b_curv[0];
        gate[b] = 1.f / (1.f + expf(-z));
    }
}

__global__ __launch_bounds__(256)
void topk_kernel(const float* __restrict__ sim, float* __restrict__ vals,
                 int* __restrict__ idx)
{
    __shared__ float sv[PM];
    __shared__ float rv[256];
    __shared__ int   ri[256];
    const int b = blockIdx.x;
    const int tid = threadIdx.x;

    for (int m = tid; m < PM; m += 256) sv[m] = sim[(size_t)b * PM + m];
    __syncthreads();

    for (int k = 0; k < PK; k++) {
        float best = -INFINITY;
        int bi = PM;
        for (int m = tid; m < PM; m += 256) {
            float v = sv[m];
            if (v > best) { best = v; bi = m; }
        }
        rv[tid] = best; ri[tid] = bi;
        __syncthreads();
        for (int off = 128; off > 0; off >>= 1) {
            if (tid < off) {
                float ov = rv[tid + off]; int oi = ri[tid + off];
                if (ov > rv[tid] || (ov == rv[tid] && oi < ri[tid])) { rv[tid] = ov; ri[tid] = oi; }
            }
            __syncthreads();
        }
        if (tid == 0) {
            vals[b * PK + k] = rv[0];
            idx[b * PK + k]  = ri[0];
            sv[ri[0]] = -INFINITY;
        }
        __syncthreads();
    }
}

__global__ __launch_bounds__(256)
void softmax_kernel(const float* __restrict__ in, float* __restrict__ out)
{
    const int b = blockIdx.x;
    const int tid = threadIdx.x;
    float loc[PM / 256];
    float mx = -INFINITY;
#pragma unroll
    for (int i = 0; i < PM / 256; i++) {
        loc[i] = in[(size_t)b * PM + tid + i * 256];
        mx = fmaxf(mx, loc[i]);
    }
    __shared__ float red[256];
    red[tid] = mx;
    __syncthreads();
    for (int off = 128; off > 0; off >>= 1) {
        if (tid < off) red[tid] = fmaxf(red[tid], red[tid + off]);
        __syncthreads();
    }
    mx = red[0];
    __syncthreads();
    float sum = 0.f;
#pragma unroll
    for (int i = 0; i < PM / 256; i++) {
        loc[i] = expf(loc[i] - mx);
        sum += loc[i];
    }
    red[tid] = sum;
    __syncthreads();
    for (int off = 128; off > 0; off >>= 1) {
        if (tid < off) red[tid] += red[tid + off];
        __syncthreads();
    }
    float inv = 1.f / red[0];
#pragma unroll
    for (int i = 0; i < PM / 256; i++)
        out[(size_t)b * PM + tid + i * 256] = loc[i] * inv;
}

__global__ __launch_bounds__(256)
void read_kernel(const float* __restrict__ vals, const int* __restrict__ idx,
                 const float* __restrict__ act, const float* __restrict__ gate,
                 const float* __restrict__ temperature, const float* __restrict__ mem,
                 float* __restrict__ readout)
{
    const int b = blockIdx.x;
    const int tid = threadIdx.x;
    __shared__ float comb[PK];
    __shared__ int   sidx[PK];

    if (tid < PK) {
        const float scale = (0.5f + gate[b]) / fmaxf(temperature[0], 1e-6f);
        const int id = idx[b * PK + tid];
        sidx[tid] = id;
        float v = vals[b * PK + tid] * scale + act[(size_t)b * PM + id];
        float mx = v;
#pragma unroll
        for (int o = 16; o > 0; o >>= 1) mx = fmaxf(mx, __shfl_xor_sync(0xffffffffu, mx, o));
        float e = expf(v - mx);
        float s = e;
#pragma unroll
        for (int o = 16; o > 0; o >>= 1) s += __shfl_xor_sync(0xffffffffu, s, o);
        comb[tid] = e / s;
    }
    __syncthreads();

    for (int h = tid; h < PH; h += 256) {
        float accv = 0.f;
#pragma unroll
        for (int k = 0; k < PK; k++)
            accv += comb[k] * mem[(size_t)sidx[k] * PH + h];
        readout[(size_t)b * PH + h] = accv;
    }
}

__global__ __launch_bounds__(256)
void bcast_kernel(const float* __restrict__ small, float* __restrict__ out)
{
    const size_t i = (size_t)blockIdx.x * blockDim.x + threadIdx.x;
    const int c = (int)(i & (PD / 4 - 1));
    const size_t bs = i / (PD / 4);
    const size_t b = bs / PS;
    float4 v = ((const float4*)small)[b * (PD / 4) + c];
    ((float4*)out)[i] = v;
}

// ===================== launch ==============================================
extern "C" void kernel_launch(void* const* d_in, const int* in_sizes, int n_in,
                              void* d_out, int out_size)
{
    const float* x      = (const float*)d_in[0];
    const float* W_enc  = (const float*)d_in[2];
    const float* b_enc  = (const float*)d_in[3];
    const float* w_curv = (const float*)d_in[4];
    const float* b_curv = (const float*)d_in[5];
    const float* memsl  = (const float*)d_in[6];
    const float* assoc  = (const float*)d_in[7];
    const float* W_dec  = (const float*)d_in[8];
    const float* b_dec  = (const float*)d_in[9];
    const float* temp   = (const float*)d_in[10];
    float* out = (float*)d_out;

    float *query, *sim, *prob, *act, *gate, *vals, *readb, *osmall;
    int* idxp;
    __nv_bfloat16 *wencTh, *wencTl, *assocTh, *assocTl, *wdecTh, *wdecTl, *memTh, *memTl;
    cudaGetSymbolAddress((void**)&query,  g_query);
    cudaGetSymbolAddress((void**)&sim,    g_sim);
    cudaGetSymbolAddress((void**)&prob,   g_prob);
    cudaGetSymbolAddress((void**)&act,    g_act);
    cudaGetSymbolAddress((void**)&gate,   g_gate);
    cudaGetSymbolAddress((void**)&vals,   g_vals);
    cudaGetSymbolAddress((void**)&idxp,   g_idx);
    cudaGetSymbolAddress((void**)&readb,  g_read);
    cudaGetSymbolAddress((void**)&osmall, g_osmall);
    cudaGetSymbolAddress((void**)&wencTh, g_wencT_h);
    cudaGetSymbolAddress((void**)&wencTl, g_wencT_l);
    cudaGetSymbolAddress((void**)&assocTh, g_assocT_h);
    cudaGetSymbolAddress((void**)&assocTl, g_assocT_l);
    cudaGetSymbolAddress((void**)&wdecTh, g_wdecT_h);
    cudaGetSymbolAddress((void**)&wdecTl, g_wdecT_l);
    cudaGetSymbolAddress((void**)&memTh,  g_memT_h);
    cudaGetSymbolAddress((void**)&memTl,  g_memT_l);

    cudaFuncSetAttribute(gemm_mma<0, 0>, cudaFuncAttributeMaxDynamicSharedMemorySize, MSMEM);
    cudaFuncSetAttribute(gemm_mma<0, 1>, cudaFuncAttributeMaxDynamicSharedMemorySize, MSMEM);
    cudaFuncSetAttribute(gemm_mma<1, 1>, cudaFuncAttributeMaxDynamicSharedMemorySize, MSMEM);
    cudaFuncSetAttribute(gemm_mma<2, 1>, cudaFuncAttributeMaxDynamicSharedMemorySize, MSMEM);

    // weight prep (transpose + bf16 hi/lo split)
    transpose_split_kernel<<<dim3(PH / 32, PD / 32), 256>>>(W_enc, wencTh, wencTl, PD, PH);
    split_kernel<<<(PM * PH / 4) / 256, 256>>>(memsl, memTh, memTl);
    transpose_split_kernel<<<dim3(PM / 32, PM / 32), 256>>>(assoc, assocTh, assocTl, PM, PM);
    transpose_split_kernel<<<dim3(PD / 32, PH / 32), 256>>>(W_dec, wdecTh, wdecTl, PH, PD);

    // 1. fused encoder: query[b][h] = mean_S tanh(x @ W_enc + b_enc)   (bf16x3)
    gemm_mma<2, 1><<<dim3(PH / 128, (PB * PS) / 128), 256, MSMEM>>>(
        x, wencTh, wencTl, b_enc, nullptr, query, PB * PS, PH, PD);

    // 2. sim_raw = query @ mem^T (round-0 act input)                    (bf16x3)
    gemm_mma<0, 1><<<dim3(PM / 128, PB / 128), 256, MSMEM>>>(
        query, memTh, memTl, nullptr, sim, nullptr, PB, PM, PH);

    // 3. gate + topk (raw sim: positive scale preserves ordering)
    gate_kernel<<<PB, 256>>>(query, w_curv, b_curv, gate);
    topk_kernel<<<PB, 256>>>(sim, vals, idxp);

    // 4. two rounds of softmax -> @assoc                                (pure bf16)
    softmax_kernel<<<PB, 256>>>(sim, prob);
    gemm_mma<0, 0><<<dim3(PM / 128, PB / 128), 256, MSMEM>>>(
        prob, assocTh, assocTl, nullptr, act, nullptr, PB, PM, PM);
    softmax_kernel<<<PB, 256>>>(act, prob);
    gemm_mma<0, 0><<<dim3(PM / 128, PB / 128), 256, MSMEM>>>(
        prob, assocTh, assocTl, nullptr, act, nullptr, PB, PM, PM);

    // 5. comb softmax + weighted memory read
    read_kernel<<<PB, 256>>>(vals, idxp, act, gate, temp, memsl, readb);

    // 6. decoder: osmall = tanh(read @ W_dec + b_dec)                   (bf16x3)
    gemm_mma<1, 1><<<dim3(PD / 128, PB / 128), 256, MSMEM>>>(
        readb, wdecTh, wdecTl, b_dec, osmall, nullptr, PB, PD, PH);

    // 7. broadcast to [B,S,D]
    bcast_kernel<<<(PB * PS * (PD / 4)) / 256, 256>>>(osmall, out);
}

// round 6
// speedup vs baseline: 3.7387x; 1.1398x over previous
#include <cuda_runtime.h>
#include <cuda_bf16.h>
#include <math.h>
#include <stdint.h>

// Problem shapes (fixed per reference)
#define PB 2048
#define PS 32
#define PD 1024
#define PH 1024
#define PM 4096
#define PK 32

// ===================== low-level helpers ====================================
__device__ __forceinline__ uint32_t smem_to_u32(const void* p) {
    uint32_t a;
    asm("{ .reg .u64 t; cvta.to.shared.u64 t, %1; cvt.u32.u64 %0, t; }" : "=r"(a) : "l"(p));
    return a;
}
__device__ __forceinline__ void ldsm_x4(uint32_t* r, uint32_t addr) {
    asm volatile("ldmatrix.sync.aligned.m8n8.x4.shared.b16 {%0,%1,%2,%3}, [%4];"
                 : "=r"(r[0]), "=r"(r[1]), "=r"(r[2]), "=r"(r[3]) : "r"(addr));
}
__device__ __forceinline__ void mma_bf16(float* d, const uint32_t* a, const uint32_t* b) {
    asm volatile(
        "mma.sync.aligned.m16n8k16.row.col.f32.bf16.bf16.f32 "
        "{%0,%1,%2,%3}, {%4,%5,%6,%7}, {%8,%9}, {%0,%1,%2,%3};\n"
        : "+f"(d[0]), "+f"(d[1]), "+f"(d[2]), "+f"(d[3])
        : "r"(a[0]), "r"(a[1]), "r"(a[2]), "r"(a[3]), "r"(b[0]), "r"(b[1]));
}
__device__ __forceinline__ void cpasync16(uint32_t s, const void* g) {
    asm volatile("cp.async.cg.shared.global [%0], [%1], 16;" :: "r"(s), "l"(g));
}
__device__ __forceinline__ void cp_commit() {
    asm volatile("cp.async.commit_group;" ::: "memory");
}

// ===================== scratch (device globals) =============================
__device__ float g_query[(size_t)PB * PH];
__device__ float g_sim[(size_t)PB * PM];
__device__ float g_act[(size_t)PB * PM];
__device__ float g_gate[PB];
__device__ float g_vals[PB * PK];
__device__ int   g_idx[PB * PK];
__device__ float g_osmall[(size_t)PB * PD];

__device__ __nv_bfloat16 g_xh[(size_t)PB * PS * PD];
__device__ __nv_bfloat16 g_xl[(size_t)PB * PS * PD];
__device__ __nv_bfloat16 g_qh[(size_t)PB * PH];
__device__ __nv_bfloat16 g_ql[(size_t)PB * PH];
__device__ __nv_bfloat16 g_probh[(size_t)PB * PM];
__device__ __nv_bfloat16 g_rh[(size_t)PB * PH];
__device__ __nv_bfloat16 g_rl[(size_t)PB * PH];

__device__ __nv_bfloat16 g_wencT_h[(size_t)PH * PD];
__device__ __nv_bfloat16 g_wencT_l[(size_t)PH * PD];
__device__ __nv_bfloat16 g_assocT_h[(size_t)PM * PM];
__device__ __nv_bfloat16 g_assocT_l[(size_t)PM * PM];   // unused by GEMM (pure bf16) but kept for prep symmetry
__device__ __nv_bfloat16 g_wdecT_h[(size_t)PD * PH];
__device__ __nv_bfloat16 g_wdecT_l[(size_t)PD * PH];
__device__ __nv_bfloat16 g_memT_h[(size_t)PM * PH];
__device__ __nv_bfloat16 g_memT_l[(size_t)PM * PH];

// ===================== bf16 hi/lo split helpers =============================
__device__ __forceinline__ void split4(float4 v, uint2& hi, uint2& lo) {
    __nv_bfloat16 h0 = __float2bfloat16_rn(v.x);
    __nv_bfloat16 h1 = __float2bfloat16_rn(v.y);
    __nv_bfloat16 h2 = __float2bfloat16_rn(v.z);
    __nv_bfloat16 h3 = __float2bfloat16_rn(v.w);
    __nv_bfloat16 l0 = __float2bfloat16_rn(v.x - __bfloat162float(h0));
    __nv_bfloat16 l1 = __float2bfloat16_rn(v.y - __bfloat162float(h1));
    __nv_bfloat16 l2 = __float2bfloat16_rn(v.z - __bfloat162float(h2));
    __nv_bfloat16 l3 = __float2bfloat16_rn(v.w - __bfloat162float(h3));
    hi.x = (uint32_t)__bfloat16_as_ushort(h0) | ((uint32_t)__bfloat16_as_ushort(h1) << 16);
    hi.y = (uint32_t)__bfloat16_as_ushort(h2) | ((uint32_t)__bfloat16_as_ushort(h3) << 16);
    lo.x = (uint32_t)__bfloat16_as_ushort(l0) | ((uint32_t)__bfloat16_as_ushort(l1) << 16);
    lo.y = (uint32_t)__bfloat16_as_ushort(l2) | ((uint32_t)__bfloat16_as_ushort(l3) << 16);
}

// ===================== prep kernels =========================================
// in [K][N] fp32 row-major -> out hi/lo [N][K] bf16 (transpose + split)
__global__ __launch_bounds__(256)
void transpose_split_kernel(const float* __restrict__ in, __nv_bfloat16* __restrict__ oh,
                            __nv_bfloat16* __restrict__ ol, int K, int N)
{
    __shared__ float t[32][33];
    const int tx = threadIdx.x & 31, ty = threadIdx.x >> 5;
    const int n_base = blockIdx.x * 32, k_base = blockIdx.y * 32;
#pragma unroll
    for (int j = 0; j < 4; j++) {
        int k = k_base + ty + j * 8;
        t[ty + j * 8][tx] = in[(size_t)k * N + n_base + tx];
    }
    __syncthreads();
#pragma unroll
    for (int j = 0; j < 4; j++) {
        int n = n_base + ty + j * 8;
        int k = k_base + tx;
        float v = t[tx][ty + j * 8];
        __nv_bfloat16 h = __float2bfloat16_rn(v);
        __nv_bfloat16 l = __float2bfloat16_rn(v - __bfloat162float(h));
        oh[(size_t)n * K + k] = h;
        ol[(size_t)n * K + k] = l;
    }
}

// elementwise fp32 -> bf16 hi/lo (for [N][K]-already and for x)
__global__ __launch_bounds__(256)
void split_kernel(const float* __restrict__ in, __nv_bfloat16* __restrict__ oh,
                  __nv_bfloat16* __restrict__ ol)
{
    const size_t i = (size_t)blockIdx.x * 256 + threadIdx.x;
    float4 v = ((const float4*)in)[i];
    uint2 hi, lo;
    split4(v, hi, lo);
    ((uint2*)oh)[i] = hi;
    ((uint2*)ol)[i] = lo;
}

// ===================== tensor-core GEMM (all-bf16 operands) =================
// C[M,N] = (Ah+Al)[M,K] * (Bh+Bl)^T   A,B row-major bf16 [rows][K]
// SPLIT=1: 3 MMAs (AhBh + AlBh + AhBl)   SPLIT=0: 1 MMA (AhBh)
// Tile 128x128, BK=32, 256 thr (8 warps x 64x32), 2-stage cp.async pipeline.
// EPI 0: C fp32   EPI 1: C = tanh(c + bias[n])
// EPI 2: per-32-row-group mean of tanh(c+bias) -> Qf fp32 + Qh/Ql bf16
#define GPAD 80u
#define OPSZ 10240u                 // 128 rows * 80 B

template <int EPI, int SPLIT>
__global__ __launch_bounds__(256, 2)
void gemm_cp(const __nv_bfloat16* __restrict__ Ah, const __nv_bfloat16* __restrict__ Al,
             const __nv_bfloat16* __restrict__ Bh, const __nv_bfloat16* __restrict__ Bl,
             const float* __restrict__ bias, float* __restrict__ C,
             float* __restrict__ Qf, __nv_bfloat16* __restrict__ Qh,
             __nv_bfloat16* __restrict__ Ql, int M, int N, int K)
{
    extern __shared__ char sm[];
    const uint32_t smb = smem_to_u32(sm);
    const int tid = threadIdx.x, wid = tid >> 5, lane = tid & 31;
    const int m0 = blockIdx.y * 128, n0 = blockIdx.x * 128;
    const int wm = (wid >> 2) * 64, wn = (wid & 3) * 32;
    const uint32_t offB = (SPLIT ? 2u : 1u) * OPSZ;
    const uint32_t STG = (SPLIT ? 4u : 2u) * OPSZ;

    float acc[4][4][4];
#pragma unroll
    for (int i = 0; i < 4; i++)
#pragma unroll
        for (int j = 0; j < 4; j++)
#pragma unroll
            for (int q = 0; q < 4; q++) acc[i][j][q] = 0.f;

    // per-thread cp.async mapping: 2 chunks per operand (512 chunks of 16B)
    const int c_row0 = tid >> 2, c_ch0 = (tid & 3);
    const int c_row1 = (tid + 256) >> 2, c_ch1 = ((tid + 256) & 3);

    // ldmatrix lane mapping
    const int lr = lane & 15;
    const int kh = (lane >> 4) ? 8 : 0;
    const int br = (lane & 7) + ((lane & 16) ? 8 : 0);
    const int bk = (lane & 8) ? 8 : 0;

    const int nch = K >> 5;

#define ISSUE(cc, bb) do {                                                         \
    const int _k0 = (cc) << 5;                                                     \
    const uint32_t _sb = smb + (bb) * STG;                                         \
    cpasync16(_sb + c_row0 * GPAD + c_ch0 * 16,                                    \
              Ah + (size_t)(m0 + c_row0) * K + _k0 + c_ch0 * 8);                   \
    cpasync16(_sb + c_row1 * GPAD + c_ch1 * 16,                                    \
              Ah + (size_t)(m0 + c_row1) * K + _k0 + c_ch1 * 8);                   \
    cpasync16(_sb + offB + c_row0 * GPAD + c_ch0 * 16,                             \
              Bh + (size_t)(n0 + c_row0) * K + _k0 + c_ch0 * 8);                   \
    cpasync16(_sb + offB + c_row1 * GPAD + c_ch1 * 16,                             \
              Bh + (size_t)(n0 + c_row1) * K + _k0 + c_ch1 * 8);                   \
    if (SPLIT) {                                                                   \
        cpasync16(_sb + OPSZ + c_row0 * GPAD + c_ch0 * 16,                         \
                  Al + (size_t)(m0 + c_row0) * K + _k0 + c_ch0 * 8);               \
        cpasync16(_sb + OPSZ + c_row1 * GPAD + c_ch1 * 16,                         \
                  Al + (size_t)(m0 + c_row1) * K + _k0 + c_ch1 * 8);               \
        cpasync16(_sb + 3u * OPSZ + c_row0 * GPAD + c_ch0 * 16,                    \
                  Bl + (size_t)(n0 + c_row0) * K + _k0 + c_ch0 * 8);               \
        cpasync16(_sb + 3u * OPSZ + c_row1 * GPAD + c_ch1 * 16,                    \
                  Bl + (size_t)(n0 + c_row1) * K + _k0 + c_ch1 * 8);               \
    }                                                                              \
    cp_commit();                                                                   \
} while (0)

    ISSUE(0, 0);

    for (int c = 0; c < nch; c++) {
        const int buf = c & 1;
        if (c + 1 < nch) {
            ISSUE(c + 1, buf ^ 1);
            asm volatile("cp.async.wait_group 1;" ::: "memory");
        } else {
            asm volatile("cp.async.wait_group 0;" ::: "memory");
        }
        __syncthreads();

        const uint32_t sb = smb + buf * STG;
#pragma unroll
        for (int ks = 0; ks < 2; ks++) {
            uint32_t ah[4][4], bhf[2][4];
#pragma unroll
            for (int mt = 0; mt < 4; mt++)
                ldsm_x4(ah[mt], sb + (wm + mt * 16 + lr) * GPAD + (ks * 16 + kh) * 2);
#pragma unroll
            for (int p = 0; p < 2; p++)
                ldsm_x4(bhf[p], sb + offB + (wn + p * 16 + br) * GPAD + (ks * 16 + bk) * 2);
#pragma unroll
            for (int mt = 0; mt < 4; mt++)
#pragma unroll
                for (int nt = 0; nt < 4; nt++)
                    mma_bf16(acc[mt][nt], ah[mt], &bhf[nt >> 1][(nt & 1) * 2]);
            if (SPLIT) {
                uint32_t al[4][4];
#pragma unroll
                for (int mt = 0; mt < 4; mt++)
                    ldsm_x4(al[mt], sb + OPSZ + (wm + mt * 16 + lr) * GPAD + (ks * 16 + kh) * 2);
#pragma unroll
                for (int mt = 0; mt < 4; mt++)
#pragma unroll
                    for (int nt = 0; nt < 4; nt++)
                        mma_bf16(acc[mt][nt], al[mt], &bhf[nt >> 1][(nt & 1) * 2]);
                uint32_t blf[2][4];
#pragma unroll
                for (int p = 0; p < 2; p++)
                    ldsm_x4(blf[p], sb + 3u * OPSZ + (wn + p * 16 + br) * GPAD + (ks * 16 + bk) * 2);
#pragma unroll
                for (int mt = 0; mt < 4; mt++)
#pragma unroll
                    for (int nt = 0; nt < 4; nt++)
                        mma_bf16(acc[mt][nt], ah[mt], &blf[nt >> 1][(nt & 1) * 2]);
            }
        }
        __syncthreads();
    }
#undef ISSUE

    // -------- epilogue: regs -> smem (padded) -> gmem -----------------------
    float* smf = (float*)sm;   // 128 x 132 floats = 67584 B
#pragma unroll
    for (int mt = 0; mt < 4; mt++) {
#pragma unroll
        for (int nt = 0; nt < 4; nt++) {
            int r = wm + mt * 16 + (lane >> 2);
            int cc = wn + nt * 8 + (lane & 3) * 2;
            float v0 = acc[mt][nt][0], v1 = acc[mt][nt][1];
            float v2 = acc[mt][nt][2], v3 = acc[mt][nt][3];
            if (EPI >= 1) {
                float b0 = bias[n0 + cc], b1 = bias[n0 + cc + 1];
                v0 = tanhf(v0 + b0); v1 = tanhf(v1 + b1);
                v2 = tanhf(v2 + b0); v3 = tanhf(v3 + b1);
            }
            smf[r * 132 + cc] = v0;
            smf[r * 132 + cc + 1] = v1;
            smf[(r + 8) * 132 + cc] = v2;
            smf[(r + 8) * 132 + cc + 1] = v3;
        }
    }
    __syncthreads();

    if (EPI == 2) {
#pragma unroll
        for (int i = 0; i < 2; i++) {
            int task = tid + i * 256;           // 512: 4 groups x 128 cols
            int grp = task >> 7, col = task & 127;
            float s = 0.f;
#pragma unroll
            for (int rr = 0; rr < 32; rr++) s += smf[(grp * 32 + rr) * 132 + col];
            s *= (1.0f / 32.0f);
            size_t qi = (size_t)(blockIdx.y * 4 + grp) * N + n0 + col;
            Qf[qi] = s;
            __nv_bfloat16 h = __float2bfloat16_rn(s);
            __nv_bfloat16 l = __float2bfloat16_rn(s - __bfloat162float(h));
            Qh[qi] = h;
            Ql[qi] = l;
        }
    } else {
#pragma unroll
        for (int i = 0; i < 16; i++) {
            int id = tid + i * 256;
            int row = id >> 5, c4 = id & 31;
            float4 o;
            o.x = smf[row * 132 + c4 * 4 + 0];
            o.y = smf[row * 132 + c4 * 4 + 1];
            o.z = smf[row * 132 + c4 * 4 + 2];
            o.w = smf[row * 132 + c4 * 4 + 3];
            *(float4*)(C + (size_t)(m0 + row) * N + n0 + c4 * 4) = o;
        }
    }
}

// ===================== small kernels =======================================
__global__ __launch_bounds__(256)
void gate_kernel(const float* __restrict__ query, const float* __restrict__ w_curv,
                 const float* __restrict__ b_curv, float* __restrict__ gate)
{
    const int b = blockIdx.x;
    const int tid = threadIdx.x;
    float s = 0.f;
    for (int h = tid; h < PH; h += 256) s += query[(size_t)b * PH + h] * w_curv[h];
    __shared__ float red[256];
    red[tid] = s;
    __syncthreads();
    for (int off = 128; off > 0; off >>= 1) {
        if (tid < off) red[tid] += red[tid + off];
        __syncthreads();
    }
    if (tid == 0) {
        float z = red[0] + b_curv[0];
        gate[b] = 1.f / (1.f + expf(-z));
    }
}

// register-resident iterative top-32 (order-agnostic downstream; ties -> lowest idx)
__global__ __launch_bounds__(256)
void topk_kernel(const float* __restrict__ sim, float* __restrict__ vals,
                 int* __restrict__ idx)
{
    const int b = blockIdx.x, tid = threadIdx.x, lane = tid & 31, wid = tid >> 5;
    const float* row = sim + (size_t)b * PM;
    float v[16];
#pragma unroll
    for (int i = 0; i < 16; i++) v[i] = row[tid + i * 256];
    float lm = -INFINITY; int ls = 0;
#pragma unroll
    for (int i = 0; i < 16; i++) if (v[i] > lm) { lm = v[i]; ls = i; }

    __shared__ float swv[8];
    __shared__ int   swi[8];
    __shared__ int   sbest;

    for (int k = 0; k < PK; k++) {
        float m = lm; int mi = ls * 256 + tid;
#pragma unroll
        for (int o = 16; o > 0; o >>= 1) {
            float ov = __shfl_xor_sync(0xffffffffu, m, o);
            int   oi = __shfl_xor_sync(0xffffffffu, mi, o);
            if (ov > m || (ov == m && oi < mi)) { m = ov; mi = oi; }
        }
        if (lane == 0) { swv[wid] = m; swi[wid] = mi; }
        __syncthreads();
        if (tid == 0) {
            float bv = swv[0]; int bi = swi[0];
#pragma unroll
            for (int w = 1; w < 8; w++)
                if (swv[w] > bv || (swv[w] == bv && swi[w] < bi)) { bv = swv[w]; bi = swi[w]; }
            vals[b * PK + k] = bv;
            idx[b * PK + k]  = bi;
            sbest = bi;
        }
        __syncthreads();
        const int bi = sbest;
        if ((bi & 255) == tid) {
            const int slot = bi >> 8;
#pragma unroll
            for (int i = 0; i < 16; i++) if (i == slot) v[i] = -INFINITY;
            lm = -INFINITY; ls = 0;
#pragma unroll
            for (int i = 0; i < 16; i++) if (v[i] > lm) { lm = v[i]; ls = i; }
        }
    }
}

// row softmax over M=4096, writes bf16 (MMA-ready A operand)
__global__ __launch_bounds__(256)
void softmax_kernel(const float* __restrict__ in, __nv_bfloat16* __restrict__ out)
{
    const int b = blockIdx.x;
    const int tid = threadIdx.x;
    float loc[PM / 256];
    float mx = -INFINITY;
#pragma unroll
    for (int i = 0; i < PM / 256; i++) {
        loc[i] = in[(size_t)b * PM + tid + i * 256];
        mx = fmaxf(mx, loc[i]);
    }
    __shared__ float red[256];
    red[tid] = mx;
    __syncthreads();
    for (int off = 128; off > 0; off >>= 1) {
        if (tid < off) red[tid] = fmaxf(red[tid], red[tid + off]);
        __syncthreads();
    }
    mx = red[0];
    __syncthreads();
    float sum = 0.f;
#pragma unroll
    for (int i = 0; i < PM / 256; i++) {
        loc[i] = expf(loc[i] - mx);
        sum += loc[i];
    }
    red[tid] = sum;
    __syncthreads();
    for (int off = 128; off > 0; off >>= 1) {
        if (tid < off) red[tid] += red[tid + off];
        __syncthreads();
    }
    float inv = 1.f / red[0];
#pragma unroll
    for (int i = 0; i < PM / 256; i++)
        out[(size_t)b * PM + tid + i * 256] = __float2bfloat16_rn(loc[i] * inv);
}

// comb softmax + weighted gather-read; writes read as bf16 hi/lo
__global__ __launch_bounds__(256)
void read_kernel(const float* __restrict__ vals, const int* __restrict__ idx,
                 const float* __restrict__ act, const float* __restrict__ gate,
                 const float* __restrict__ temperature, const float* __restrict__ mem,
                 __nv_bfloat16* __restrict__ rh, __nv_bfloat16* __restrict__ rl)
{
    const int b = blockIdx.x;
    const int tid = threadIdx.x;
    __shared__ float comb[PK];
    __shared__ int   sidx[PK];

    if (tid < PK) {
        const float scale = (0.5f + gate[b]) / fmaxf(temperature[0], 1e-6f);
        const int id = idx[b * PK + tid];
        sidx[tid] = id;
        float v = vals[b * PK + tid] * scale + act[(size_t)b * PM + id];
        float mx = v;
#pragma unroll
        for (int o = 16; o > 0; o >>= 1) mx = fmaxf(mx, __shfl_xor_sync(0xffffffffu, mx, o));
        float e = expf(v - mx);
        float s = e;
#pragma unroll
        for (int o = 16; o > 0; o >>= 1) s += __shfl_xor_sync(0xffffffffu, s, o);
        comb[tid] = e / s;
    }
    __syncthreads();

    for (int h = tid; h < PH; h += 256) {
        float accv = 0.f;
#pragma unroll
        for (int k = 0; k < PK; k++)
            accv += comb[k] * mem[(size_t)sidx[k] * PH + h];
        __nv_bfloat16 hh = __float2bfloat16_rn(accv);
        __nv_bfloat16 ll = __float2bfloat16_rn(accv - __bfloat162float(hh));
        rh[(size_t)b * PH + h] = hh;
        rl[(size_t)b * PH + h] = ll;
    }
}

__global__ __launch_bounds__(256)
void bcast_kernel(const float* __restrict__ small, float* __restrict__ out)
{
    const size_t i = (size_t)blockIdx.x * blockDim.x + threadIdx.x;
    const int c = (int)(i & (PD / 4 - 1));
    const size_t bs = i / (PD / 4);
    const size_t b = bs / PS;
    float4 v = ((const float4*)small)[b * (PD / 4) + c];
    ((float4*)out)[i] = v;
}

// ===================== launch ==============================================
#define SMEM_SPLIT 81920u
#define SMEM_NS    67584u

extern "C" void kernel_launch(void* const* d_in, const int* in_sizes, int n_in,
                              void* d_out, int out_size)
{
    const float* x      = (const float*)d_in[0];
    const float* W_enc  = (const float*)d_in[2];
    const float* b_enc  = (const float*)d_in[3];
    const float* w_curv = (const float*)d_in[4];
    const float* b_curv = (const float*)d_in[5];
    const float* memsl  = (const float*)d_in[6];
    const float* assoc  = (const float*)d_in[7];
    const float* W_dec  = (const float*)d_in[8];
    const float* b_dec  = (const float*)d_in[9];
    const float* temp   = (const float*)d_in[10];
    float* out = (float*)d_out;

    float *query, *sim, *act, *gate, *vals, *osmall;
    int* idxp;
    __nv_bfloat16 *xh, *xl, *qh, *ql, *probh, *rh, *rl;
    __nv_bfloat16 *wencTh, *wencTl, *assocTh, *assocTl, *wdecTh, *wdecTl, *memTh, *memTl;
    cudaGetSymbolAddress((void**)&query,  g_query);
    cudaGetSymbolAddress((void**)&sim,    g_sim);
    cudaGetSymbolAddress((void**)&act,    g_act);
    cudaGetSymbolAddress((void**)&gate,   g_gate);
    cudaGetSymbolAddress((void**)&vals,   g_vals);
    cudaGetSymbolAddress((void**)&idxp,   g_idx);
    cudaGetSymbolAddress((void**)&osmall, g_osmall);
    cudaGetSymbolAddress((void**)&xh,     g_xh);
    cudaGetSymbolAddress((void**)&xl,     g_xl);
    cudaGetSymbolAddress((void**)&qh,     g_qh);
    cudaGetSymbolAddress((void**)&ql,     g_ql);
    cudaGetSymbolAddress((void**)&probh,  g_probh);
    cudaGetSymbolAddress((void**)&rh,     g_rh);
    cudaGetSymbolAddress((void**)&rl,     g_rl);
    cudaGetSymbolAddress((void**)&wencTh, g_wencT_h);
    cudaGetSymbolAddress((void**)&wencTl, g_wencT_l);
    cudaGetSymbolAddress((void**)&assocTh, g_assocT_h);
    cudaGetSymbolAddress((void**)&assocTl, g_assocT_l);
    cudaGetSymbolAddress((void**)&wdecTh, g_wdecT_h);
    cudaGetSymbolAddress((void**)&wdecTl, g_wdecT_l);
    cudaGetSymbolAddress((void**)&memTh,  g_memT_h);
    cudaGetSymbolAddress((void**)&memTl,  g_memT_l);

    cudaFuncSetAttribute(gemm_cp<0, 0>, cudaFuncAttributeMaxDynamicSharedMemorySize, SMEM_NS);
    cudaFuncSetAttribute(gemm_cp<0, 1>, cudaFuncAttributeMaxDynamicSharedMemorySize, SMEM_SPLIT);
    cudaFuncSetAttribute(gemm_cp<1, 1>, cudaFuncAttributeMaxDynamicSharedMemorySize, SMEM_SPLIT);
    cudaFuncSetAttribute(gemm_cp<2, 1>, cudaFuncAttributeMaxDynamicSharedMemorySize, SMEM_SPLIT);

    // ---- prep: all operands to MMA-ready bf16 hi/lo ----
    split_kernel<<<(PB * PS * PD / 4) / 256, 256>>>(x, xh, xl);
    transpose_split_kernel<<<dim3(PH / 32, PD / 32), 256>>>(W_enc, wencTh, wencTl, PD, PH);
    split_kernel<<<(PM * PH / 4) / 256, 256>>>(memsl, memTh, memTl);
    transpose_split_kernel<<<dim3(PM / 32, PM / 32), 256>>>(assoc, assocTh, assocTl, PM, PM);
    transpose_split_kernel<<<dim3(PD / 32, PH / 32), 256>>>(W_dec, wdecTh, wdecTl, PH, PD);

    // 1. fused encoder: query = mean_S tanh(x @ W_enc + b_enc)   (bf16x3)
    gemm_cp<2, 1><<<dim3(PH / 128, (PB * PS) / 128), 256, SMEM_SPLIT>>>(
        xh, xl, wencTh, wencTl, b_enc, nullptr, query, qh, ql, PB * PS, PH, PD);

    // 2. sim_raw = query @ mem^T (round-0 act input)              (bf16x3)
    gemm_cp<0, 1><<<dim3(PM / 128, PB / 128), 256, SMEM_SPLIT>>>(
        qh, ql, memTh, memTl, nullptr, sim, nullptr, nullptr, nullptr, PB, PM, PH);

    // 3. gate + topk (raw sim; positive scale preserves ordering)
    gate_kernel<<<PB, 256>>>(query, w_curv, b_curv, gate);
    topk_kernel<<<PB, 256>>>(sim, vals, idxp);

    // 4. two rounds of softmax -> @assoc                          (pure bf16)
    softmax_kernel<<<PB, 256>>>(sim, probh);
    gemm_cp<0, 0><<<dim3(PM / 128, PB / 128), 256, SMEM_NS>>>(
        probh, nullptr, assocTh, nullptr, nullptr, act, nullptr, nullptr, nullptr, PB, PM, PM);
    softmax_kernel<<<PB, 256>>>(act, probh);
    gemm_cp<0, 0><<<dim3(PM / 128, PB / 128), 256, SMEM_NS>>>(
        probh, nullptr, assocTh, nullptr, nullptr, act, nullptr, nullptr, nullptr, PB, PM, PM);

    // 5. comb softmax + weighted memory read -> rh/rl
    read_kernel<<<PB, 256>>>(vals, idxp, act, gate, temp, memsl, rh, rl);

    // 6. decoder: osmall = tanh(read @ W_dec + b_dec)             (bf16x3)
    gemm_cp<1, 1><<<dim3(PD / 128, PB / 128), 256, SMEM_SPLIT>>>(
        rh, rl, wdecTh, wdecTl, b_dec, osmall, nullptr, nullptr, nullptr, PB, PD, PH);

    // 7. broadcast to [B,S,D]
    bcast_kernel<<<(PB * PS * (PD / 4)) / 256, 256>>>(osmall, out);
}

// round 8
// speedup vs baseline: 3.8268x; 1.0236x over previous
#include <cuda_runtime.h>
#include <cuda_bf16.h>
#include <cuda_fp8.h>
#include <math.h>
#include <stdint.h>

// Problem shapes (fixed per reference)
#define PB 2048
#define PS 32
#define PD 1024
#define PH 1024
#define PM 4096
#define PK 32

// ===================== low-level helpers ====================================
__device__ __forceinline__ uint32_t smem_to_u32(const void* p) {
    uint32_t a;
    asm("{ .reg .u64 t; cvta.to.shared.u64 t, %1; cvt.u32.u64 %0, t; }" : "=r"(a) : "l"(p));
    return a;
}
__device__ __forceinline__ void ldsm_x4(uint32_t* r, uint32_t addr) {
    asm volatile("ldmatrix.sync.aligned.m8n8.x4.shared.b16 {%0,%1,%2,%3}, [%4];"
                 : "=r"(r[0]), "=r"(r[1]), "=r"(r[2]), "=r"(r[3]) : "r"(addr));
}
__device__ __forceinline__ void mma_bf16(float* d, const uint32_t* a, const uint32_t* b) {
    asm volatile(
        "mma.sync.aligned.m16n8k16.row.col.f32.bf16.bf16.f32 "
        "{%0,%1,%2,%3}, {%4,%5,%6,%7}, {%8,%9}, {%0,%1,%2,%3};\n"
        : "+f"(d[0]), "+f"(d[1]), "+f"(d[2]), "+f"(d[3])
        : "r"(a[0]), "r"(a[1]), "r"(a[2]), "r"(a[3]), "r"(b[0]), "r"(b[1]));
}
__device__ __forceinline__ void mma_e4m3(float* d, const uint32_t* a, const uint32_t* b) {
    asm volatile(
        "mma.sync.aligned.m16n8k32.row.col.f32.e4m3.e4m3.f32 "
        "{%0,%1,%2,%3}, {%4,%5,%6,%7}, {%8,%9}, {%0,%1,%2,%3};\n"
        : "+f"(d[0]), "+f"(d[1]), "+f"(d[2]), "+f"(d[3])
        : "r"(a[0]), "r"(a[1]), "r"(a[2]), "r"(a[3]), "r"(b[0]), "r"(b[1]));
}
__device__ __forceinline__ void cpasync16(uint32_t s, const void* g) {
    asm volatile("cp.async.cg.shared.global [%0], [%1], 16;" :: "r"(s), "l"(g));
}
__device__ __forceinline__ void cp_commit() {
    asm volatile("cp.async.commit_group;" ::: "memory");
}

// ===================== scratch (device globals) =============================
__device__ float g_query[(size_t)PB * PH];
__device__ float g_sim[(size_t)PB * PM];
__device__ float g_act[(size_t)PB * PM];
__device__ float g_gate[PB];
__device__ float g_vals[PB * PK];
__device__ int   g_idx[PB * PK];
__device__ float g_osmall[(size_t)PB * PD];

__device__ __nv_bfloat16 g_xh[(size_t)PB * PS * PD];
__device__ __nv_bfloat16 g_xl[(size_t)PB * PS * PD];
__device__ __nv_bfloat16 g_qh[(size_t)PB * PH];
__device__ __nv_bfloat16 g_ql[(size_t)PB * PH];
__device__ __nv_bfloat16 g_rh[(size_t)PB * PH];
__device__ __nv_bfloat16 g_rl[(size_t)PB * PH];

__device__ uint8_t g_prob8[(size_t)PB * PM];           // e4m3, prob*256
__device__ uint8_t g_assoc8[(size_t)PM * PM];          // e4m3, assoc^T*256, [N][K]

__device__ __nv_bfloat16 g_wencT_h[(size_t)PH * PD];
__device__ __nv_bfloat16 g_wencT_l[(size_t)PH * PD];
__device__ __nv_bfloat16 g_wdecT_h[(size_t)PD * PH];
__device__ __nv_bfloat16 g_wdecT_l[(size_t)PD * PH];
__device__ __nv_bfloat16 g_memT_h[(size_t)PM * PH];
__device__ __nv_bfloat16 g_memT_l[(size_t)PM * PH];

// ===================== bf16 hi/lo split helpers =============================
__device__ __forceinline__ void split4(float4 v, uint2& hi, uint2& lo) {
    __nv_bfloat16 h0 = __float2bfloat16_rn(v.x);
    __nv_bfloat16 h1 = __float2bfloat16_rn(v.y);
    __nv_bfloat16 h2 = __float2bfloat16_rn(v.z);
    __nv_bfloat16 h3 = __float2bfloat16_rn(v.w);
    __nv_bfloat16 l0 = __float2bfloat16_rn(v.x - __bfloat162float(h0));
    __nv_bfloat16 l1 = __float2bfloat16_rn(v.y - __bfloat162float(h1));
    __nv_bfloat16 l2 = __float2bfloat16_rn(v.z - __bfloat162float(h2));
    __nv_bfloat16 l3 = __float2bfloat16_rn(v.w - __bfloat162float(h3));
    hi.x = (uint32_t)__bfloat16_as_ushort(h0) | ((uint32_t)__bfloat16_as_ushort(h1) << 16);
    hi.y = (uint32_t)__bfloat16_as_ushort(h2) | ((uint32_t)__bfloat16_as_ushort(h3) << 16);
    lo.x = (uint32_t)__bfloat16_as_ushort(l0) | ((uint32_t)__bfloat16_as_ushort(l1) << 16);
    lo.y = (uint32_t)__bfloat16_as_ushort(l2) | ((uint32_t)__bfloat16_as_ushort(l3) << 16);
}
__device__ __forceinline__ uint8_t to_e4m3(float v) {
    __nv_fp8_e4m3 f(v);
    return *(uint8_t*)&f;
}

// ===================== prep kernels =========================================
// in [K][N] fp32 row-major -> out hi/lo [N][K] bf16 (transpose + split)
__global__ __launch_bounds__(256)
void transpose_split_kernel(const float* __restrict__ in, __nv_bfloat16* __restrict__ oh,
                            __nv_bfloat16* __restrict__ ol, int K, int N)
{
    __shared__ float t[32][33];
    const int tx = threadIdx.x & 31, ty = threadIdx.x >> 5;
    const int n_base = blockIdx.x * 32, k_base = blockIdx.y * 32;
#pragma unroll
    for (int j = 0; j < 4; j++) {
        int k = k_base + ty + j * 8;
        t[ty + j * 8][tx] = in[(size_t)k * N + n_base + tx];
    }
    __syncthreads();
#pragma unroll
    for (int j = 0; j < 4; j++) {
        int n = n_base + ty + j * 8;
        int k = k_base + tx;
        float v = t[tx][ty + j * 8];
        __nv_bfloat16 h = __float2bfloat16_rn(v);
        __nv_bfloat16 l = __float2bfloat16_rn(v - __bfloat162float(h));
        oh[(size_t)n * K + k] = h;
        ol[(size_t)n * K + k] = l;
    }
}

// in [K][N] fp32 -> out [N][K] e4m3 scaled by 256
__global__ __launch_bounds__(256)
void transpose_fp8_kernel(const float* __restrict__ in, uint8_t* __restrict__ o8,
                          int K, int N)
{
    __shared__ float t[32][33];
    const int tx = threadIdx.x & 31, ty = threadIdx.x >> 5;
    const int n_base = blockIdx.x * 32, k_base = blockIdx.y * 32;
#pragma unroll
    for (int j = 0; j < 4; j++) {
        int k = k_base + ty + j * 8;
        t[ty + j * 8][tx] = in[(size_t)k * N + n_base + tx];
    }
    __syncthreads();
#pragma unroll
    for (int j = 0; j < 4; j++) {
        int n = n_base + ty + j * 8;
        int k = k_base + tx;
        o8[(size_t)n * K + k] = to_e4m3(t[tx][ty + j * 8] * 256.0f);
    }
}

// elementwise fp32 -> bf16 hi/lo
__global__ __launch_bounds__(256)
void split_kernel(const float* __restrict__ in, __nv_bfloat16* __restrict__ oh,
                  __nv_bfloat16* __restrict__ ol)
{
    const size_t i = (size_t)blockIdx.x * 256 + threadIdx.x;
    float4 v = ((const float4*)in)[i];
    uint2 hi, lo;
    split4(v, hi, lo);
    ((uint2*)oh)[i] = hi;
    ((uint2*)ol)[i] = lo;
}

// ===================== bf16 tensor-core GEMM (split3) =======================
// C[M,N] = (Ah+Al)[M,K] * (Bh+Bl)^T   all row-major bf16 [rows][K]
// Tile 128x128, BK=32, 256 thr (8 warps x 64x32), 2-stage cp.async pipeline.
// EPI 0: C fp32   EPI 1: C = tanh(c + bias[n])
// EPI 2: per-32-row-group mean of tanh(c+bias) -> Qf fp32 + Qh/Ql bf16
#define GPAD 80u
#define OPSZ 10240u                 // 128 rows * 80 B

template <int EPI>
__global__ __launch_bounds__(256, 2)
void gemm_cp(const __nv_bfloat16* __restrict__ Ah, const __nv_bfloat16* __restrict__ Al,
             const __nv_bfloat16* __restrict__ Bh, const __nv_bfloat16* __restrict__ Bl,
             const float* __restrict__ bias, float* __restrict__ C,
             float* __restrict__ Qf, __nv_bfloat16* __restrict__ Qh,
             __nv_bfloat16* __restrict__ Ql, int M, int N, int K)
{
    extern __shared__ char sm[];
    const uint32_t smb = smem_to_u32(sm);
    const int tid = threadIdx.x, wid = tid >> 5, lane = tid & 31;
    const int m0 = blockIdx.y * 128, n0 = blockIdx.x * 128;
    const int wm = (wid >> 2) * 64, wn = (wid & 3) * 32;
    const uint32_t offB = 2u * OPSZ;
    const uint32_t STG = 4u * OPSZ;

    float acc[4][4][4];
#pragma unroll
    for (int i = 0; i < 4; i++)
#pragma unroll
        for (int j = 0; j < 4; j++)
#pragma unroll
            for (int q = 0; q < 4; q++) acc[i][j][q] = 0.f;

    const int c_row0 = tid >> 2, c_ch0 = (tid & 3);
    const int c_row1 = (tid + 256) >> 2, c_ch1 = ((tid + 256) & 3);

    const int lr = lane & 15;
    const int kh = (lane >> 4) ? 8 : 0;
    const int br = (lane & 7) + ((lane & 16) ? 8 : 0);
    const int bk = (lane & 8) ? 8 : 0;

    const int nch = K >> 5;

#define ISSUE(cc, bb) do {                                                         \
    const int _k0 = (cc) << 5;                                                     \
    const uint32_t _sb = smb + (bb) * STG;                                         \
    cpasync16(_sb + c_row0 * GPAD + c_ch0 * 16,                                    \
              Ah + (size_t)(m0 + c_row0) * K + _k0 + c_ch0 * 8);                   \
    cpasync16(_sb + c_row1 * GPAD + c_ch1 * 16,                                    \
              Ah + (size_t)(m0 + c_row1) * K + _k0 + c_ch1 * 8);                   \
    cpasync16(_sb + offB + c_row0 * GPAD + c_ch0 * 16,                             \
              Bh + (size_t)(n0 + c_row0) * K + _k0 + c_ch0 * 8);                   \
    cpasync16(_sb + offB + c_row1 * GPAD + c_ch1 * 16,                             \
              Bh + (size_t)(n0 + c_row1) * K + _k0 + c_ch1 * 8);                   \
    cpasync16(_sb + OPSZ + c_row0 * GPAD + c_ch0 * 16,                             \
              Al + (size_t)(m0 + c_row0) * K + _k0 + c_ch0 * 8);                   \
    cpasync16(_sb + OPSZ + c_row1 * GPAD + c_ch1 * 16,                             \
              Al + (size_t)(m0 + c_row1) * K + _k0 + c_ch1 * 8);                   \
    cpasync16(_sb + 3u * OPSZ + c_row0 * GPAD + c_ch0 * 16,                        \
              Bl + (size_t)(n0 + c_row0) * K + _k0 + c_ch0 * 8);                   \
    cpasync16(_sb + 3u * OPSZ + c_row1 * GPAD + c_ch1 * 16,                        \
              Bl + (size_t)(n0 + c_row1) * K + _k0 + c_ch1 * 8);                   \
    cp_commit();                                                                   \
} while (0)

    ISSUE(0, 0);

    for (int c = 0; c < nch; c++) {
        const int buf = c & 1;
        if (c + 1 < nch) {
            ISSUE(c + 1, buf ^ 1);
            asm volatile("cp.async.wait_group 1;" ::: "memory");
        } else {
            asm volatile("cp.async.wait_group 0;" ::: "memory");
        }
        __syncthreads();

        const uint32_t sb = smb + buf * STG;
#pragma unroll
        for (int ks = 0; ks < 2; ks++) {
            uint32_t ah[4][4], bhf[2][4];
#pragma unroll
            for (int mt = 0; mt < 4; mt++)
                ldsm_x4(ah[mt], sb + (wm + mt * 16 + lr) * GPAD + (ks * 16 + kh) * 2);
#pragma unroll
            for (int p = 0; p < 2; p++)
                ldsm_x4(bhf[p], sb + offB + (wn + p * 16 + br) * GPAD + (ks * 16 + bk) * 2);
#pragma unroll
            for (int mt = 0; mt < 4; mt++)
#pragma unroll
                for (int nt = 0; nt < 4; nt++)
                    mma_bf16(acc[mt][nt], ah[mt], &bhf[nt >> 1][(nt & 1) * 2]);
            {
                uint32_t al[4][4];
#pragma unroll
                for (int mt = 0; mt < 4; mt++)
                    ldsm_x4(al[mt], sb + OPSZ + (wm + mt * 16 + lr) * GPAD + (ks * 16 + kh) * 2);
#pragma unroll
                for (int mt = 0; mt < 4; mt++)
#pragma unroll
                    for (int nt = 0; nt < 4; nt++)
                        mma_bf16(acc[mt][nt], al[mt], &bhf[nt >> 1][(nt & 1) * 2]);
                uint32_t blf[2][4];
#pragma unroll
                for (int p = 0; p < 2; p++)
                    ldsm_x4(blf[p], sb + 3u * OPSZ + (wn + p * 16 + br) * GPAD + (ks * 16 + bk) * 2);
#pragma unroll
                for (int mt = 0; mt < 4; mt++)
#pragma unroll
                    for (int nt = 0; nt < 4; nt++)
                        mma_bf16(acc[mt][nt], ah[mt], &blf[nt >> 1][(nt & 1) * 2]);
            }
        }
        __syncthreads();
    }
#undef ISSUE

    // -------- epilogue: regs -> smem (padded) -> gmem -----------------------
    float* smf = (float*)sm;   // 128 x 132 floats = 67584 B
#pragma unroll
    for (int mt = 0; mt < 4; mt++) {
#pragma unroll
        for (int nt = 0; nt < 4; nt++) {
            int r = wm + mt * 16 + (lane >> 2);
            int cc = wn + nt * 8 + (lane & 3) * 2;
            float v0 = acc[mt][nt][0], v1 = acc[mt][nt][1];
            float v2 = acc[mt][nt][2], v3 = acc[mt][nt][3];
            if (EPI >= 1) {
                float b0 = bias[n0 + cc], b1 = bias[n0 + cc + 1];
                v0 = tanhf(v0 + b0); v1 = tanhf(v1 + b1);
                v2 = tanhf(v2 + b0); v3 = tanhf(v3 + b1);
            }
            smf[r * 132 + cc] = v0;
            smf[r * 132 + cc + 1] = v1;
            smf[(r + 8) * 132 + cc] = v2;
            smf[(r + 8) * 132 + cc + 1] = v3;
        }
    }
    __syncthreads();

    if (EPI == 2) {
#pragma unroll
        for (int i = 0; i < 2; i++) {
            int task = tid + i * 256;           // 512: 4 groups x 128 cols
            int grp = task >> 7, col = task & 127;
            float s = 0.f;
#pragma unroll
            for (int rr = 0; rr < 32; rr++) s += smf[(grp * 32 + rr) * 132 + col];
            s *= (1.0f / 32.0f);
            size_t qi = (size_t)(blockIdx.y * 4 + grp) * N + n0 + col;
            Qf[qi] = s;
            __nv_bfloat16 h = __float2bfloat16_rn(s);
            __nv_bfloat16 l = __float2bfloat16_rn(s - __bfloat162float(h));
            Qh[qi] = h;
            Ql[qi] = l;
        }
    } else {
#pragma unroll
        for (int i = 0; i < 16; i++) {
            int id = tid + i * 256;
            int row = id >> 5, c4 = id & 31;
            float4 o;
            o.x = smf[row * 132 + c4 * 4 + 0];
            o.y = smf[row * 132 + c4 * 4 + 1];
            o.z = smf[row * 132 + c4 * 4 + 2];
            o.w = smf[row * 132 + c4 * 4 + 3];
            *(float4*)(C + (size_t)(m0 + row) * N + n0 + c4 * 4) = o;
        }
    }
}

// ===================== fp8 tensor-core GEMM (assoc) =========================
// C[M,N] = (A*256)[M,K]e4m3 * ((B*256)[N][K]e4m3)^T * 2^-16
// Tile 128x128, BK=64 bytes, 2-stage cp.async, m16n8k32 e4m3 MMA.
__global__ __launch_bounds__(256, 2)
void gemm_fp8(const uint8_t* __restrict__ A, const uint8_t* __restrict__ B,
              float* __restrict__ C, int M, int N, int K)
{
    extern __shared__ char sm[];
    const uint32_t smb = smem_to_u32(sm);
    const int tid = threadIdx.x, wid = tid >> 5, lane = tid & 31;
    const int m0 = blockIdx.y * 128, n0 = blockIdx.x * 128;
    const int wm = (wid >> 2) * 64, wn = (wid & 3) * 32;
    const uint32_t offB = OPSZ;
    const uint32_t STG = 2u * OPSZ;

    float acc[4][4][4];
#pragma unroll
    for (int i = 0; i < 4; i++)
#pragma unroll
        for (int j = 0; j < 4; j++)
#pragma unroll
            for (int q = 0; q < 4; q++) acc[i][j][q] = 0.f;

    const int c_row0 = tid >> 2, c_ch0 = (tid & 3);
    const int c_row1 = (tid + 256) >> 2, c_ch1 = ((tid + 256) & 3);

    const int lr = lane & 15;
    const int khb = (lane >> 4) ? 16 : 0;                 // byte offset within 32B k-step
    const int br = (lane & 7) + ((lane & 16) ? 8 : 0);
    const int bkb = (lane & 8) ? 16 : 0;

    const int nch = K >> 6;                               // 64 fp8 per chunk

#define ISSUE8(cc, bb) do {                                                        \
    const int _k0 = (cc) << 6;                                                     \
    const uint32_t _sb = smb + (bb) * STG;                                         \
    cpasync16(_sb + c_row0 * GPAD + c_ch0 * 16,                                    \
              A + (size_t)(m0 + c_row0) * K + _k0 + c_ch0 * 16);                   \
    cpasync16(_sb + c_row1 * GPAD + c_ch1 * 16,                                    \
              A + (size_t)(m0 + c_row1) * K + _k0 + c_ch1 * 16);                   \
    cpasync16(_sb + offB + c_row0 * GPAD + c_ch0 * 16,                             \
              B + (size_t)(n0 + c_row0) * K + _k0 + c_ch0 * 16);                   \
    cpasync16(_sb + offB + c_row1 * GPAD + c_ch1 * 16,                             \
              B + (size_t)(n0 + c_row1) * K + _k0 + c_ch1 * 16);                   \
    cp_commit();                                                                   \
} while (0)

    ISSUE8(0, 0);

    for (int c = 0; c < nch; c++) {
        const int buf = c & 1;
        if (c + 1 < nch) {
            ISSUE8(c + 1, buf ^ 1);
            asm volatile("cp.async.wait_group 1;" ::: "memory");
        } else {
            asm volatile("cp.async.wait_group 0;" ::: "memory");
        }
        __syncthreads();

        const uint32_t sb = smb + buf * STG;
#pragma unroll
        for (int ks = 0; ks < 2; ks++) {                  // 2 x 32-byte k-steps
            uint32_t ah[4][4], bhf[2][4];
#pragma unroll
            for (int mt = 0; mt < 4; mt++)
                ldsm_x4(ah[mt], sb + (wm + mt * 16 + lr) * GPAD + ks * 32 + khb);
#pragma unroll
            for (int p = 0; p < 2; p++)
                ldsm_x4(bhf[p], sb + offB + (wn + p * 16 + br) * GPAD + ks * 32 + bkb);
#pragma unroll
            for (int mt = 0; mt < 4; mt++)
#pragma unroll
                for (int nt = 0; nt < 4; nt++)
                    mma_e4m3(acc[mt][nt], ah[mt], &bhf[nt >> 1][(nt & 1) * 2]);
        }
        __syncthreads();
    }
#undef ISSUE8

    // epilogue with 2^-16 descale
    float* smf = (float*)sm;
    const float DS = 1.0f / 65536.0f;
#pragma unroll
    for (int mt = 0; mt < 4; mt++) {
#pragma unroll
        for (int nt = 0; nt < 4; nt++) {
            int r = wm + mt * 16 + (lane >> 2);
            int cc = wn + nt * 8 + (lane & 3) * 2;
            smf[r * 132 + cc]           = acc[mt][nt][0] * DS;
            smf[r * 132 + cc + 1]       = acc[mt][nt][1] * DS;
            smf[(r + 8) * 132 + cc]     = acc[mt][nt][2] * DS;
            smf[(r + 8) * 132 + cc + 1] = acc[mt][nt][3] * DS;
        }
    }
    __syncthreads();
#pragma unroll
    for (int i = 0; i < 16; i++) {
        int id = tid + i * 256;
        int row = id >> 5, c4 = id & 31;
        float4 o;
        o.x = smf[row * 132 + c4 * 4 + 0];
        o.y = smf[row * 132 + c4 * 4 + 1];
        o.z = smf[row * 132 + c4 * 4 + 2];
        o.w = smf[row * 132 + c4 * 4 + 3];
        *(float4*)(C + (size_t)(m0 + row) * N + n0 + c4 * 4) = o;
    }
}

// ===================== small kernels =======================================
__global__ __launch_bounds__(256)
void gate_kernel(const float* __restrict__ query, const float* __restrict__ w_curv,
                 const float* __restrict__ b_curv, float* __restrict__ gate)
{
    const int b = blockIdx.x;
    const int tid = threadIdx.x;
    float s = 0.f;
    for (int h = tid; h < PH; h += 256) s += query[(size_t)b * PH + h] * w_curv[h];
    __shared__ float red[256];
    red[tid] = s;
    __syncthreads();
    for (int off = 128; off > 0; off >>= 1) {
        if (tid < off) red[tid] += red[tid + off];
        __syncthreads();
    }
    if (tid == 0) {
        float z = red[0] + b_curv[0];
        gate[b] = 1.f / (1.f + expf(-z));
    }
}

// register-resident iterative top-32
__global__ __launch_bounds__(256)
void topk_kernel(const float* __restrict__ sim, float* __restrict__ vals,
                 int* __restrict__ idx)
{
    const int b = blockIdx.x, tid = threadIdx.x, lane = tid & 31, wid = tid >> 5;
    const float* row = sim + (size_t)b * PM;
    float v[16];
#pragma unroll
    for (int i = 0; i < 16; i++) v[i] = row[tid + i * 256];
    float lm = -INFINITY; int ls = 0;
#pragma unroll
    for (int i = 0; i < 16; i++) if (v[i] > lm) { lm = v[i]; ls = i; }

    __shared__ float swv[8];
    __shared__ int   swi[8];
    __shared__ int   sbest;

    for (int k = 0; k < PK; k++) {
        float m = lm; int mi = ls * 256 + tid;
#pragma unroll
        for (int o = 16; o > 0; o >>= 1) {
            float ov = __shfl_xor_sync(0xffffffffu, m, o);
            int   oi = __shfl_xor_sync(0xffffffffu, mi, o);
            if (ov > m || (ov == m && oi < mi)) { m = ov; mi = oi; }
        }
        if (lane == 0) { swv[wid] = m; swi[wid] = mi; }
        __syncthreads();
        if (tid == 0) {
            float bv = swv[0]; int bi = swi[0];
#pragma unroll
            for (int w = 1; w < 8; w++)
                if (swv[w] > bv || (swv[w] == bv && swi[w] < bi)) { bv = swv[w]; bi = swi[w]; }
            vals[b * PK + k] = bv;
            idx[b * PK + k]  = bi;
            sbest = bi;
        }
        __syncthreads();
        const int bi = sbest;
        if ((bi & 255) == tid) {
            const int slot = bi >> 8;
#pragma unroll
            for (int i = 0; i < 16; i++) if (i == slot) v[i] = -INFINITY;
            lm = -INFINITY; ls = 0;
#pragma unroll
            for (int i = 0; i < 16; i++) if (v[i] > lm) { lm = v[i]; ls = i; }
        }
    }
}

// row softmax over M=4096, writes e4m3 scaled by 256 (MMA-ready A operand)
__global__ __launch_bounds__(256)
void softmax_kernel(const float* __restrict__ in, uint8_t* __restrict__ out)
{
    const int b = blockIdx.x;
    const int tid = threadIdx.x;
    float loc[PM / 256];
    float mx = -INFINITY;
#pragma unroll
    for (int i = 0; i < PM / 256; i++) {
        loc[i] = in[(size_t)b * PM + tid + i * 256];
        mx = fmaxf(mx, loc[i]);
    }
    __shared__ float red[256];
    red[tid] = mx;
    __syncthreads();
    for (int off = 128; off > 0; off >>= 1) {
        if (tid < off) red[tid] = fmaxf(red[tid], red[tid + off]);
        __syncthreads();
    }
    mx = red[0];
    __syncthreads();
    float sum = 0.f;
#pragma unroll
    for (int i = 0; i < PM / 256; i++) {
        loc[i] = expf(loc[i] - mx);
        sum += loc[i];
    }
    red[tid] = sum;
    __syncthreads();
    for (int off = 128; off > 0; off >>= 1) {
        if (tid < off) red[tid] += red[tid + off];
        __syncthreads();
    }
    float inv = 256.0f / red[0];
#pragma unroll
    for (int i = 0; i < PM / 256; i++)
        out[(size_t)b * PM + tid + i * 256] = to_e4m3(loc[i] * inv);
}

// comb softmax + weighted gather-read; writes read as bf16 hi/lo
__global__ __launch_bounds__(256)
void read_kernel(const float* __restrict__ vals, const int* __restrict__ idx,
                 const float* __restrict__ act, const float* __restrict__ gate,
                 const float* __restrict__ temperature, const float* __restrict__ mem,
                 __nv_bfloat16* __restrict__ rh, __nv_bfloat16* __restrict__ rl)
{
    const int b = blockIdx.x;
    const int tid = threadIdx.x;
    __shared__ float comb[PK];
    __shared__ int   sidx[PK];

    if (tid < PK) {
        const float scale = (0.5f + gate[b]) / fmaxf(temperature[0], 1e-6f);
        const int id = idx[b * PK + tid];
        sidx[tid] = id;
        float v = vals[b * PK + tid] * scale + act[(size_t)b * PM + id];
        float mx = v;
#pragma unroll
        for (int o = 16; o > 0; o >>= 1) mx = fmaxf(mx, __shfl_xor_sync(0xffffffffu, mx, o));
        float e = expf(v - mx);
        float s = e;
#pragma unroll
        for (int o = 16; o > 0; o >>= 1) s += __shfl_xor_sync(0xffffffffu, s, o);
        comb[tid] = e / s;
    }
    __syncthreads();

    for (int h = tid; h < PH; h += 256) {
        float accv = 0.f;
#pragma unroll
        for (int k = 0; k < PK; k++)
            accv += comb[k] * mem[(size_t)sidx[k] * PH + h];
        __nv_bfloat16 hh = __float2bfloat16_rn(accv);
        __nv_bfloat16 ll = __float2bfloat16_rn(accv - __bfloat162float(hh));
        rh[(size_t)b * PH + h] = hh;
        rl[(size_t)b * PH + h] = ll;
    }
}

__global__ __launch_bounds__(256)
void bcast_kernel(const float* __restrict__ small, float* __restrict__ out)
{
    const size_t i = (size_t)blockIdx.x * blockDim.x + threadIdx.x;
    const int c = (int)(i & (PD / 4 - 1));
    const size_t bs = i / (PD / 4);
    const size_t b = bs / PS;
    float4 v = ((const float4*)small)[b * (PD / 4) + c];
    ((float4*)out)[i] = v;
}

// ===================== launch ==============================================
#define SMEM_SPLIT 81920u
#define SMEM_F8    67584u

extern "C" void kernel_launch(void* const* d_in, const int* in_sizes, int n_in,
                              void* d_out, int out_size)
{
    const float* x      = (const float*)d_in[0];
    const float* W_enc  = (const float*)d_in[2];
    const float* b_enc  = (const float*)d_in[3];
    const float* w_curv = (const float*)d_in[4];
    const float* b_curv = (const float*)d_in[5];
    const float* memsl  = (const float*)d_in[6];
    const float* assoc  = (const float*)d_in[7];
    const float* W_dec  = (const float*)d_in[8];
    const float* b_dec  = (const float*)d_in[9];
    const float* temp   = (const float*)d_in[10];
    float* out = (float*)d_out;

    float *query, *sim, *act, *gate, *vals, *osmall;
    int* idxp;
    __nv_bfloat16 *xh, *xl, *qh, *ql, *rh, *rl;
    __nv_bfloat16 *wencTh, *wencTl, *wdecTh, *wdecTl, *memTh, *memTl;
    uint8_t *prob8, *assoc8;
    cudaGetSymbolAddress((void**)&query,  g_query);
    cudaGetSymbolAddress((void**)&sim,    g_sim);
    cudaGetSymbolAddress((void**)&act,    g_act);
    cudaGetSymbolAddress((void**)&gate,   g_gate);
    cudaGetSymbolAddress((void**)&vals,   g_vals);
    cudaGetSymbolAddress((void**)&idxp,   g_idx);
    cudaGetSymbolAddress((void**)&osmall, g_osmall);
    cudaGetSymbolAddress((void**)&xh,     g_xh);
    cudaGetSymbolAddress((void**)&xl,     g_xl);
    cudaGetSymbolAddress((void**)&qh,     g_qh);
    cudaGetSymbolAddress((void**)&ql,     g_ql);
    cudaGetSymbolAddress((void**)&rh,     g_rh);
    cudaGetSymbolAddress((void**)&rl,     g_rl);
    cudaGetSymbolAddress((void**)&prob8,  g_prob8);
    cudaGetSymbolAddress((void**)&assoc8, g_assoc8);
    cudaGetSymbolAddress((void**)&wencTh, g_wencT_h);
    cudaGetSymbolAddress((void**)&wencTl, g_wencT_l);
    cudaGetSymbolAddress((void**)&wdecTh, g_wdecT_h);
    cudaGetSymbolAddress((void**)&wdecTl, g_wdecT_l);
    cudaGetSymbolAddress((void**)&memTh,  g_memT_h);
    cudaGetSymbolAddress((void**)&memTl,  g_memT_l);

    cudaFuncSetAttribute(gemm_cp<0>, cudaFuncAttributeMaxDynamicSharedMemorySize, SMEM_SPLIT);
    cudaFuncSetAttribute(gemm_cp<1>, cudaFuncAttributeMaxDynamicSharedMemorySize, SMEM_SPLIT);
    cudaFuncSetAttribute(gemm_cp<2>, cudaFuncAttributeMaxDynamicSharedMemorySize, SMEM_SPLIT);
    cudaFuncSetAttribute(gemm_fp8,   cudaFuncAttributeMaxDynamicSharedMemorySize, SMEM_F8);

    // ---- prep ----
    split_kernel<<<(PB * PS * PD / 4) / 256, 256>>>(x, xh, xl);
    transpose_split_kernel<<<dim3(PH / 32, PD / 32), 256>>>(W_enc, wencTh, wencTl, PD, PH);
    split_kernel<<<(PM * PH / 4) / 256, 256>>>(memsl, memTh, memTl);
    transpose_fp8_kernel<<<dim3(PM / 32, PM / 32), 256>>>(assoc, assoc8, PM, PM);
    transpose_split_kernel<<<dim3(PD / 32, PH / 32), 256>>>(W_dec, wdecTh, wdecTl, PH, PD);

    // 1. fused encoder: query = mean_S tanh(x @ W_enc + b_enc)   (bf16x3)
    gemm_cp<2><<<dim3(PH / 128, (PB * PS) / 128), 256, SMEM_SPLIT>>>(
        xh, xl, wencTh, wencTl, b_enc, nullptr, query, qh, ql, PB * PS, PH, PD);

    // 2. sim_raw = query @ mem^T (round-0 act input)              (bf16x3)
    gemm_cp<0><<<dim3(PM / 128, PB / 128), 256, SMEM_SPLIT>>>(
        qh, ql, memTh, memTl, nullptr, sim, nullptr, nullptr, nullptr, PB, PM, PH);

    // 3. gate + topk (raw sim; positive scale preserves ordering)
    gate_kernel<<<PB, 256>>>(query, w_curv, b_curv, gate);
    topk_kernel<<<PB, 256>>>(sim, vals, idxp);

    // 4. two rounds of softmax -> @assoc                          (e4m3 fp8)
    softmax_kernel<<<PB, 256>>>(sim, prob8);
    gemm_fp8<<<dim3(PM / 128, PB / 128), 256, SMEM_F8>>>(prob8, assoc8, act, PB, PM, PM);
    softmax_kernel<<<PB, 256>>>(act, prob8);
    gemm_fp8<<<dim3(PM / 128, PB / 128), 256, SMEM_F8>>>(prob8, assoc8, act, PB, PM, PM);

    // 5. comb softmax + weighted memory read -> rh/rl
    read_kernel<<<PB, 256>>>(vals, idxp, act, gate, temp, memsl, rh, rl);

    // 6. decoder: osmall = tanh(read @ W_dec + b_dec)             (bf16x3)
    gemm_cp<1><<<dim3(PD / 128, PB / 128), 256, SMEM_SPLIT>>>(
        rh, rl, wdecTh, wdecTl, b_dec, osmall, nullptr, nullptr, nullptr, PB, PD, PH);

    // 7. broadcast to [B,S,D]
    bcast_kernel<<<(PB * PS * (PD / 4)) / 256, 256>>>(osmall, out);
}